// round 5
// baseline (speedup 1.0000x reference)
#include <cuda_runtime.h>

#define NUM_B 2
#define SEQ   2048
#define HD    64
#define NH    12
#define NEGV  (-99999.0f)
#define TOT   (NUM_B*NH*SEQ*HD)
#define N_ITEMS (16*24)   // (qx, bh) work items
#define N_CTAS  296       // 148 SMs x 2 CTAs

typedef unsigned long long u64;

// ---- packed f32x2 helpers (sm_103a FFMA2 path) ----
__device__ __forceinline__ u64 bc2(float x) {
    u64 r; asm("mov.b64 %0, {%1, %1};" : "=l"(r) : "f"(x)); return r;
}
__device__ __forceinline__ void fma2(u64 &d, u64 a, u64 b) {
    asm("fma.rn.f32x2 %0, %1, %2, %0;" : "+l"(d) : "l"(a), "l"(b));
}
__device__ __forceinline__ void mul2(u64 &d, u64 a) {
    asm("mul.rn.f32x2 %0, %0, %1;" : "+l"(d) : "l"(a));
}
__device__ __forceinline__ void add2(u64 &d, u64 a) {
    asm("add.rn.f32x2 %0, %0, %1;" : "+l"(d) : "l"(a));
}
__device__ __forceinline__ float2 unpk2(u64 a) {
    float2 f; asm("mov.b64 {%0, %1}, %2;" : "=f"(f.x), "=f"(f.y) : "l"(a)); return f;
}

// ---- cp.async helpers ----
__device__ __forceinline__ void cp16(float* smem_dst, const float* gmem_src) {
    unsigned s = (unsigned)__cvta_generic_to_shared(smem_dst);
    asm volatile("cp.async.ca.shared.global [%0], [%1], 16;\n" :: "r"(s), "l"(gmem_src));
}
__device__ __forceinline__ void cp_commit() {
    asm volatile("cp.async.commit_group;\n");
}
__device__ __forceinline__ void cp_wait0() {
    asm volatile("cp.async.wait_group 0;\n" ::: "memory");
}

// Scratch (allocation-free rule: __device__ globals)
__device__ float g_Q[TOT];
__device__ float g_K[TOT];
__device__ float g_V[TOT];
__device__ float g_Oa[TOT];
__device__ int   g_counter;

__global__ void reset_counter() { g_counter = 0; }

// ---------------------------------------------------------------------------
// Kernel 1: fused Q/K/V projection, single-sync.  x[4096,64] @ W[64,768] + b,
// all three W tiles staged at once; a-operands packed once and reused 3x.
// Block = 64 rows x one head (64 cols).  Dynamic smem 69.6KB.
// ---------------------------------------------------------------------------
#define QKV_SMEM_FLOATS (4*64*68)
#define QKV_SMEM_BYTES  (QKV_SMEM_FLOATS*4)

__global__ __launch_bounds__(256) void qkv_kernel(
    const float* __restrict__ x,
    const float* __restrict__ Wq, const float* __restrict__ bq,
    const float* __restrict__ Wk, const float* __restrict__ bk,
    const float* __restrict__ Wv, const float* __restrict__ bv)
{
    extern __shared__ float smq[];
    float* xs = smq;                 // [64][68]
    float* ws0 = xs  + 64*68;        // Wq tile
    float* ws1 = ws0 + 64*68;        // Wk tile
    float* ws2 = ws1 + 64*68;        // Wv tile
    const int tile = blockIdx.x;   // 0..63
    const int h    = blockIdx.y;   // head
    const int tid  = threadIdx.x;
    const int tx   = tid & 15;
    const int ty   = tid >> 4;

    #pragma unroll
    for (int i = tid; i < 1024; i += 256) {
        const int r = i >> 4, c4 = (i & 15) << 2;
        *reinterpret_cast<float4*>(&xs[r*68 + c4]) =
            *reinterpret_cast<const float4*>(x + (tile*64 + r)*64 + c4);
        *reinterpret_cast<float4*>(&ws0[r*68 + c4]) =
            *reinterpret_cast<const float4*>(Wq + r*768 + h*64 + c4);
        *reinterpret_cast<float4*>(&ws1[r*68 + c4]) =
            *reinterpret_cast<const float4*>(Wk + r*768 + h*64 + c4);
        *reinterpret_cast<float4*>(&ws2[r*68 + c4]) =
            *reinterpret_cast<const float4*>(Wv + r*768 + h*64 + c4);
    }
    __syncthreads();

    u64 acc[3][4][2];
    #pragma unroll
    for (int m = 0; m < 3; m++)
        #pragma unroll
        for (int i = 0; i < 4; i++) { acc[m][i][0] = 0ull; acc[m][i][1] = 0ull; }

    #pragma unroll 4
    for (int kk = 0; kk < 64; kk += 4) {
        // pack a-operands once (4 rows x 4 k-vals)
        u64 ax[4][4];
        #pragma unroll
        for (int i = 0; i < 4; i++) {
            float4 t = *reinterpret_cast<const float4*>(&xs[(ty*4+i)*68 + kk]);
            ax[i][0] = bc2(t.x); ax[i][1] = bc2(t.y);
            ax[i][2] = bc2(t.z); ax[i][3] = bc2(t.w);
        }
        const float* wsm[3] = {ws0, ws1, ws2};
        #pragma unroll
        for (int m = 0; m < 3; m++) {
            const float* w = wsm[m];
            ulonglong2 b0 = *reinterpret_cast<const ulonglong2*>(&w[(kk+0)*68 + tx*4]);
            ulonglong2 b1 = *reinterpret_cast<const ulonglong2*>(&w[(kk+1)*68 + tx*4]);
            ulonglong2 b2 = *reinterpret_cast<const ulonglong2*>(&w[(kk+2)*68 + tx*4]);
            ulonglong2 b3 = *reinterpret_cast<const ulonglong2*>(&w[(kk+3)*68 + tx*4]);
            #pragma unroll
            for (int i = 0; i < 4; i++) {
                fma2(acc[m][i][0], ax[i][0], b0.x); fma2(acc[m][i][1], ax[i][0], b0.y);
                fma2(acc[m][i][0], ax[i][1], b1.x); fma2(acc[m][i][1], ax[i][1], b1.y);
                fma2(acc[m][i][0], ax[i][2], b2.x); fma2(acc[m][i][1], ax[i][2], b2.y);
                fma2(acc[m][i][0], ax[i][3], b3.x); fma2(acc[m][i][1], ax[i][3], b3.y);
            }
        }
    }

    const float* Bm[3] = {bq, bk, bv};
    float* Om[3] = {g_Q, g_K, g_V};
    #pragma unroll
    for (int m = 0; m < 3; m++) {
        const ulonglong2 bias =
            *reinterpret_cast<const ulonglong2*>(Bm[m] + h*64 + tx*4);
        float* __restrict__ O = Om[m];
        #pragma unroll
        for (int i = 0; i < 4; i++) {
            const int rg = tile*64 + ty*4 + i;
            const int bi = rg >> 11;            // /SEQ
            const int si = rg & (SEQ-1);
            add2(acc[m][i][0], bias.x);
            add2(acc[m][i][1], bias.y);
            ulonglong2 o; o.x = acc[m][i][0]; o.y = acc[m][i][1];
            *reinterpret_cast<ulonglong2*>(O + ((bi*NH + h)*SEQ + si)*HD + tx*4) = o;
        }
    }
}

// ---------------------------------------------------------------------------
// Kernel 2: flash attention, fp32, fixed-max softmax, persistent work queue,
// FFMA2 matmuls, SOFTWARE-PIPELINED staging:
//   K(t+1) prefetched into registers (LDG lands during tile-t compute);
//   V(t) fetched via cp.async issued before QK, waited just before PV.
// Quirky mask: col>row OR score==0 -> NEG (faithful to tril(scores)==0).
// ---------------------------------------------------------------------------
#define ATTN_SMEM_FLOATS ((128 + 64 + 64 + 128) * 68)
#define ATTN_SMEM_BYTES  (ATTN_SMEM_FLOATS * 4)

__global__ __launch_bounds__(256, 2) void attn_kernel()
{
    extern __shared__ float sm[];
    float* Qs = sm;                  // [128][68]  (row, d)
    float* Ks = Qs + 128*68;         // [64][68]   (d, key)  -- transposed
    float* Vs = Ks + 64*68;          // [64][68]   (key, d)
    float* Ps = Vs + 64*68;          // [128][68]  (row, key)
    __shared__ int s_item;

    const int tid = threadIdx.x;
    const int tx  = tid & 15;
    const int ty  = tid >> 4;
    // per-thread staging coords (4 chunks of 16B)
    const int sr0 = tid >> 4;          // rows 0..15 (+16 per chunk)
    const int sc4 = (tid & 15) << 2;   // col group

    for (;;) {
        __syncthreads();             // previous item fully done
        if (tid == 0) s_item = atomicAdd(&g_counter, 1);
        __syncthreads();
        const int it = s_item;
        if (it >= N_ITEMS) return;

        const int qr = it / 24;      // 0..15
        const int qx = 15 - qr;      // longest first
        const int bh = it - qr * 24;
        const int qb  = qx * 128;
        const int off = bh * SEQ * HD;

        #pragma unroll
        for (int i = tid; i < 2048; i += 256) {
            const int r = i >> 4, c4 = (i & 15) << 2;
            *reinterpret_cast<float4*>(&Qs[r*68 + c4]) =
                *reinterpret_cast<const float4*>(g_Q + off + (qb + r)*64 + c4);
        }

        // prefetch K tile 0 into registers
        float4 kreg[4];
        #pragma unroll
        for (int j = 0; j < 4; j++) {
            const int r = sr0 + j*16;
            kreg[j] = *reinterpret_cast<const float4*>(g_K + off + r*64 + sc4);
        }

        float l_i[8];
        u64 acc[8][2];
        #pragma unroll
        for (int i = 0; i < 8; i++) {
            l_i[i] = 0.f;
            acc[i][0] = 0ull; acc[i][1] = 0ull;
        }

        const int nkt = 2*qx + 2;    // causal: keys up to qb+127
        for (int kt = 0; kt < nkt; ++kt) {
            const int kb = kt * 64;
            __syncthreads();         // prev PV done: Ks/Vs free
            // store prefetched K (transposed d-major)
            #pragma unroll
            for (int j = 0; j < 4; j++) {
                const int r = sr0 + j*16;
                Ks[(sc4+0)*68 + r] = kreg[j].x;
                Ks[(sc4+1)*68 + r] = kreg[j].y;
                Ks[(sc4+2)*68 + r] = kreg[j].z;
                Ks[(sc4+3)*68 + r] = kreg[j].w;
            }
            __syncthreads();         // Ks (and Qs on first tile) visible

            // prefetch next K tile into registers (lands during compute)
            if (kt + 1 < nkt) {
                const int kb2 = kb + 64;
                #pragma unroll
                for (int j = 0; j < 4; j++) {
                    const int r = sr0 + j*16;
                    kreg[j] = *reinterpret_cast<const float4*>(
                        g_K + off + (kb2 + r)*64 + sc4);
                }
            }
            // async-copy current V tile (covered by QK compute below)
            #pragma unroll
            for (int j = 0; j < 4; j++) {
                const int r = sr0 + j*16;
                cp16(&Vs[r*68 + sc4], g_V + off + (kb + r)*64 + sc4);
            }
            cp_commit();

            // ---- S = Q @ K^T  (8 rows x 2 f32x2-pairs per thread) ----
            u64 s2[8][2];
            #pragma unroll
            for (int i = 0; i < 8; i++) { s2[i][0] = 0ull; s2[i][1] = 0ull; }

            #pragma unroll 4
            for (int kk = 0; kk < 64; kk += 4) {
                ulonglong2 b0 = *reinterpret_cast<const ulonglong2*>(&Ks[(kk+0)*68 + tx*4]);
                ulonglong2 b1 = *reinterpret_cast<const ulonglong2*>(&Ks[(kk+1)*68 + tx*4]);
                ulonglong2 b2 = *reinterpret_cast<const ulonglong2*>(&Ks[(kk+2)*68 + tx*4]);
                ulonglong2 b3 = *reinterpret_cast<const ulonglong2*>(&Ks[(kk+3)*68 + tx*4]);
                #pragma unroll
                for (int i = 0; i < 8; i++) {
                    float4 t = *reinterpret_cast<const float4*>(&Qs[(ty*8+i)*68 + kk]);
                    u64 a;
                    a = bc2(t.x); fma2(s2[i][0], a, b0.x); fma2(s2[i][1], a, b0.y);
                    a = bc2(t.y); fma2(s2[i][0], a, b1.x); fma2(s2[i][1], a, b1.y);
                    a = bc2(t.z); fma2(s2[i][0], a, b2.x); fma2(s2[i][1], a, b2.y);
                    a = bc2(t.w); fma2(s2[i][0], a, b3.x); fma2(s2[i][1], a, b3.y);
                }
            }

            // ---- mask + exp (fixed max = 0) + partial row sums + write P ----
            const int row0 = qb + ty*8;
            const int col0 = kb + tx*4;
            #pragma unroll
            for (int i = 0; i < 8; i++) {
                const int row = row0 + i;
                float2 u0 = unpk2(s2[i][0]);
                float2 u1 = unpk2(s2[i][1]);
                float s0 = u0.x, s1 = u0.y, s2v = u1.x, s3 = u1.y;
                if ((col0 + 0 > row) || (s0  == 0.0f)) s0  = NEGV;
                if ((col0 + 1 > row) || (s1  == 0.0f)) s1  = NEGV;
                if ((col0 + 2 > row) || (s2v == 0.0f)) s2v = NEGV;
                if ((col0 + 3 > row) || (s3  == 0.0f)) s3  = NEGV;
                const float p0 = __expf(s0);
                const float p1 = __expf(s1);
                const float p2 = __expf(s2v);
                const float p3 = __expf(s3);
                l_i[i] += (p0 + p1) + (p2 + p3);
                *reinterpret_cast<float4*>(&Ps[(ty*8+i)*68 + tx*4]) =
                    make_float4(p0, p1, p2, p3);
            }
            cp_wait0();              // V landed
            __syncthreads();         // Ps + Vs visible

            // ---- acc += P @ V ----
            #pragma unroll 4
            for (int kk = 0; kk < 64; kk += 4) {
                ulonglong2 b0 = *reinterpret_cast<const ulonglong2*>(&Vs[(kk+0)*68 + tx*4]);
                ulonglong2 b1 = *reinterpret_cast<const ulonglong2*>(&Vs[(kk+1)*68 + tx*4]);
                ulonglong2 b2 = *reinterpret_cast<const ulonglong2*>(&Vs[(kk+2)*68 + tx*4]);
                ulonglong2 b3 = *reinterpret_cast<const ulonglong2*>(&Vs[(kk+3)*68 + tx*4]);
                #pragma unroll
                for (int i = 0; i < 8; i++) {
                    float4 t = *reinterpret_cast<const float4*>(&Ps[(ty*8+i)*68 + kk]);
                    u64 a;
                    a = bc2(t.x); fma2(acc[i][0], a, b0.x); fma2(acc[i][1], a, b0.y);
                    a = bc2(t.y); fma2(acc[i][0], a, b1.x); fma2(acc[i][1], a, b1.y);
                    a = bc2(t.z); fma2(acc[i][0], a, b2.x); fma2(acc[i][1], a, b2.y);
                    a = bc2(t.w); fma2(acc[i][0], a, b3.x); fma2(acc[i][1], a, b3.y);
                }
            }
        }

        // ---- epilogue: reduce row sums across the 16 tx lanes, normalize ----
        #pragma unroll
        for (int i = 0; i < 8; i++) {
            float l = l_i[i];
            #pragma unroll
            for (int o_ = 8; o_; o_ >>= 1)
                l += __shfl_xor_sync(0xffffffffu, l, o_);
            const u64 inv2 = bc2(1.0f / l);
            mul2(acc[i][0], inv2);
            mul2(acc[i][1], inv2);
            ulonglong2 o; o.x = acc[i][0]; o.y = acc[i][1];
            *reinterpret_cast<ulonglong2*>(g_Oa + off + (qb + ty*8 + i)*64 + tx*4) = o;
        }
    }
}

// ---------------------------------------------------------------------------
// Kernel 3: output projection.  merge-heads(O)[4096,768] @ Wo[768,64] + bo.
// Block: 32 rows x 64 cols, K looped over 12 heads of 64.
// ---------------------------------------------------------------------------
__global__ __launch_bounds__(256) void proj_kernel(
    const float* __restrict__ Wo, const float* __restrict__ bo,
    float* __restrict__ out)
{
    __shared__ float As[32*68];
    __shared__ float Ws[64*68];
    const int blk = blockIdx.x;     // 0..127, 32 rows each
    const int tid = threadIdx.x;
    const int tx  = tid & 15;
    const int ty  = tid >> 4;

    u64 acc[2][2];
    #pragma unroll
    for (int i = 0; i < 2; i++) { acc[i][0] = 0ull; acc[i][1] = 0ull; }

    #pragma unroll 1
    for (int h = 0; h < NH; ++h) {
        __syncthreads();
        #pragma unroll
        for (int i = tid; i < 512; i += 256) {
            const int r = i >> 4, c4 = (i & 15) << 2;
            const int rg = blk*32 + r;
            const int bi = rg >> 11;
            const int si = rg & (SEQ-1);
            *reinterpret_cast<float4*>(&As[r*68 + c4]) =
                *reinterpret_cast<const float4*>(g_Oa + ((bi*NH + h)*SEQ + si)*HD + c4);
        }
        #pragma unroll
        for (int i = tid; i < 1024; i += 256) {
            const int k = i >> 4, c4 = (i & 15) << 2;
            *reinterpret_cast<float4*>(&Ws[k*68 + c4]) =
                *reinterpret_cast<const float4*>(Wo + (h*64 + k)*64 + c4);
        }
        __syncthreads();

        #pragma unroll 4
        for (int kk = 0; kk < 64; kk += 4) {
            ulonglong2 b0 = *reinterpret_cast<const ulonglong2*>(&Ws[(kk+0)*68 + tx*4]);
            ulonglong2 b1 = *reinterpret_cast<const ulonglong2*>(&Ws[(kk+1)*68 + tx*4]);
            ulonglong2 b2 = *reinterpret_cast<const ulonglong2*>(&Ws[(kk+2)*68 + tx*4]);
            ulonglong2 b3 = *reinterpret_cast<const ulonglong2*>(&Ws[(kk+3)*68 + tx*4]);
            #pragma unroll
            for (int i = 0; i < 2; i++) {
                float4 t = *reinterpret_cast<const float4*>(&As[(ty*2+i)*68 + kk]);
                u64 a;
                a = bc2(t.x); fma2(acc[i][0], a, b0.x); fma2(acc[i][1], a, b0.y);
                a = bc2(t.y); fma2(acc[i][0], a, b1.x); fma2(acc[i][1], a, b1.y);
                a = bc2(t.z); fma2(acc[i][0], a, b2.x); fma2(acc[i][1], a, b2.y);
                a = bc2(t.w); fma2(acc[i][0], a, b3.x); fma2(acc[i][1], a, b3.y);
            }
        }
    }

    const ulonglong2 bias = *reinterpret_cast<const ulonglong2*>(bo + tx*4);
    #pragma unroll
    for (int i = 0; i < 2; i++) {
        const int rg = blk*32 + ty*2 + i;
        add2(acc[i][0], bias.x);
        add2(acc[i][1], bias.y);
        ulonglong2 o; o.x = acc[i][0]; o.y = acc[i][1];
        *reinterpret_cast<ulonglong2*>(out + rg*64 + tx*4) = o;
    }
}

// ---------------------------------------------------------------------------
extern "C" void kernel_launch(void* const* d_in, const int* in_sizes, int n_in,
                              void* d_out, int out_size)
{
    (void)in_sizes; (void)n_in; (void)out_size;
    const float* x  = (const float*)d_in[0];
    const float* Wq = (const float*)d_in[1];
    const float* bq = (const float*)d_in[2];
    const float* Wk = (const float*)d_in[3];
    const float* bk = (const float*)d_in[4];
    const float* Wv = (const float*)d_in[5];
    const float* bv = (const float*)d_in[6];
    const float* Wo = (const float*)d_in[7];
    const float* bo = (const float*)d_in[8];
    float* out = (float*)d_out;

    cudaFuncSetAttribute(attn_kernel,
                         cudaFuncAttributeMaxDynamicSharedMemorySize,
                         ATTN_SMEM_BYTES);
    cudaFuncSetAttribute(qkv_kernel,
                         cudaFuncAttributeMaxDynamicSharedMemorySize,
                         QKV_SMEM_BYTES);

    reset_counter<<<1, 1>>>();
    qkv_kernel<<<dim3(64, 12), 256, QKV_SMEM_BYTES>>>(x, Wq, bq, Wk, bk, Wv, bv);
    attn_kernel<<<N_CTAS, 256, ATTN_SMEM_BYTES>>>();
    proj_kernel<<<128, 256>>>(Wo, bo, out);
}

// round 6
// speedup vs baseline: 1.0014x; 1.0014x over previous
#include <cuda_runtime.h>

#define NUM_B 2
#define SEQ   2048
#define HD    64
#define NH    12
#define NEGV  (-99999.0f)
#define TOT   (NUM_B*NH*SEQ*HD)
#define N_ITEMS (16*24)   // (qx, bh) work items
#define N_CTAS  296       // 148 SMs x 2 CTAs

typedef unsigned long long u64;

// ---- packed f32x2 helpers (sm_103a FFMA2 path) ----
__device__ __forceinline__ u64 bc2(float x) {
    u64 r; asm("mov.b64 %0, {%1, %1};" : "=l"(r) : "f"(x)); return r;
}
__device__ __forceinline__ void fma2(u64 &d, u64 a, u64 b) {
    asm("fma.rn.f32x2 %0, %1, %2, %0;" : "+l"(d) : "l"(a), "l"(b));
}
__device__ __forceinline__ void mul2(u64 &d, u64 a) {
    asm("mul.rn.f32x2 %0, %0, %1;" : "+l"(d) : "l"(a));
}
__device__ __forceinline__ void add2(u64 &d, u64 a) {
    asm("add.rn.f32x2 %0, %0, %1;" : "+l"(d) : "l"(a));
}
__device__ __forceinline__ float2 unpk2(u64 a) {
    float2 f; asm("mov.b64 {%0, %1}, %2;" : "=f"(f.x), "=f"(f.y) : "l"(a)); return f;
}

// ---- cp.async helpers ----
__device__ __forceinline__ void cp16(float* smem_dst, const float* gmem_src) {
    unsigned s = (unsigned)__cvta_generic_to_shared(smem_dst);
    asm volatile("cp.async.ca.shared.global [%0], [%1], 16;\n" :: "r"(s), "l"(gmem_src));
}
__device__ __forceinline__ void cp_commit() {
    asm volatile("cp.async.commit_group;\n");
}
__device__ __forceinline__ void cp_wait0() {
    asm volatile("cp.async.wait_group 0;\n" ::: "memory");
}

// Scratch (allocation-free rule: __device__ globals)
__device__ float g_Q[TOT];
__device__ float g_K[TOT];
__device__ float g_V[TOT];
__device__ float g_Oa[TOT];
__device__ int   g_counter;

__global__ void reset_counter() { g_counter = 0; }

// ---------------------------------------------------------------------------
// Kernel 1: fused Q/K/V projection, single-sync.  x[4096,64] @ W[64,768] + b,
// all three W tiles staged at once; a-operands packed once and reused 3x.
// Block = 64 rows x one head (64 cols).  Dynamic smem 69.6KB.
// ---------------------------------------------------------------------------
#define QKV_SMEM_FLOATS (4*64*68)
#define QKV_SMEM_BYTES  (QKV_SMEM_FLOATS*4)

__global__ __launch_bounds__(256) void qkv_kernel(
    const float* __restrict__ x,
    const float* __restrict__ Wq, const float* __restrict__ bq,
    const float* __restrict__ Wk, const float* __restrict__ bk,
    const float* __restrict__ Wv, const float* __restrict__ bv)
{
    extern __shared__ float smq[];
    float* xs = smq;                 // [64][68]
    float* ws0 = xs  + 64*68;        // Wq tile
    float* ws1 = ws0 + 64*68;        // Wk tile
    float* ws2 = ws1 + 64*68;        // Wv tile
    const int tile = blockIdx.x;   // 0..63
    const int h    = blockIdx.y;   // head
    const int tid  = threadIdx.x;
    const int tx   = tid & 15;
    const int ty   = tid >> 4;

    #pragma unroll
    for (int i = tid; i < 1024; i += 256) {
        const int r = i >> 4, c4 = (i & 15) << 2;
        *reinterpret_cast<float4*>(&xs[r*68 + c4]) =
            *reinterpret_cast<const float4*>(x + (tile*64 + r)*64 + c4);
        *reinterpret_cast<float4*>(&ws0[r*68 + c4]) =
            *reinterpret_cast<const float4*>(Wq + r*768 + h*64 + c4);
        *reinterpret_cast<float4*>(&ws1[r*68 + c4]) =
            *reinterpret_cast<const float4*>(Wk + r*768 + h*64 + c4);
        *reinterpret_cast<float4*>(&ws2[r*68 + c4]) =
            *reinterpret_cast<const float4*>(Wv + r*768 + h*64 + c4);
    }
    __syncthreads();

    u64 acc[3][4][2];
    #pragma unroll
    for (int m = 0; m < 3; m++)
        #pragma unroll
        for (int i = 0; i < 4; i++) { acc[m][i][0] = 0ull; acc[m][i][1] = 0ull; }

    #pragma unroll 4
    for (int kk = 0; kk < 64; kk += 4) {
        // pack a-operands once (4 rows x 4 k-vals)
        u64 ax[4][4];
        #pragma unroll
        for (int i = 0; i < 4; i++) {
            float4 t = *reinterpret_cast<const float4*>(&xs[(ty*4+i)*68 + kk]);
            ax[i][0] = bc2(t.x); ax[i][1] = bc2(t.y);
            ax[i][2] = bc2(t.z); ax[i][3] = bc2(t.w);
        }
        const float* wsm[3] = {ws0, ws1, ws2};
        #pragma unroll
        for (int m = 0; m < 3; m++) {
            const float* w = wsm[m];
            ulonglong2 b0 = *reinterpret_cast<const ulonglong2*>(&w[(kk+0)*68 + tx*4]);
            ulonglong2 b1 = *reinterpret_cast<const ulonglong2*>(&w[(kk+1)*68 + tx*4]);
            ulonglong2 b2 = *reinterpret_cast<const ulonglong2*>(&w[(kk+2)*68 + tx*4]);
            ulonglong2 b3 = *reinterpret_cast<const ulonglong2*>(&w[(kk+3)*68 + tx*4]);
            #pragma unroll
            for (int i = 0; i < 4; i++) {
                fma2(acc[m][i][0], ax[i][0], b0.x); fma2(acc[m][i][1], ax[i][0], b0.y);
                fma2(acc[m][i][0], ax[i][1], b1.x); fma2(acc[m][i][1], ax[i][1], b1.y);
                fma2(acc[m][i][0], ax[i][2], b2.x); fma2(acc[m][i][1], ax[i][2], b2.y);
                fma2(acc[m][i][0], ax[i][3], b3.x); fma2(acc[m][i][1], ax[i][3], b3.y);
            }
        }
    }

    const float* Bm[3] = {bq, bk, bv};
    float* Om[3] = {g_Q, g_K, g_V};
    #pragma unroll
    for (int m = 0; m < 3; m++) {
        const ulonglong2 bias =
            *reinterpret_cast<const ulonglong2*>(Bm[m] + h*64 + tx*4);
        float* __restrict__ O = Om[m];
        #pragma unroll
        for (int i = 0; i < 4; i++) {
            const int rg = tile*64 + ty*4 + i;
            const int bi = rg >> 11;            // /SEQ
            const int si = rg & (SEQ-1);
            add2(acc[m][i][0], bias.x);
            add2(acc[m][i][1], bias.y);
            ulonglong2 o; o.x = acc[m][i][0]; o.y = acc[m][i][1];
            *reinterpret_cast<ulonglong2*>(O + ((bi*NH + h)*SEQ + si)*HD + tx*4) = o;
        }
    }
}

// ---------------------------------------------------------------------------
// Kernel 2: flash attention, fp32, fixed-max softmax, persistent work queue,
// FFMA2 matmuls, SOFTWARE-PIPELINED staging:
//   K(t+1) prefetched into registers (LDG lands during tile-t compute);
//   V(t) fetched via cp.async issued before QK, waited just before PV.
// Quirky mask: col>row OR score==0 -> NEG (faithful to tril(scores)==0).
// ---------------------------------------------------------------------------
#define ATTN_SMEM_FLOATS ((128 + 64 + 64 + 128) * 68)
#define ATTN_SMEM_BYTES  (ATTN_SMEM_FLOATS * 4)

__global__ __launch_bounds__(256, 2) void attn_kernel()
{
    extern __shared__ float sm[];
    float* Qs = sm;                  // [128][68]  (row, d)
    float* Ks = Qs + 128*68;         // [64][68]   (d, key)  -- transposed
    float* Vs = Ks + 64*68;          // [64][68]   (key, d)
    float* Ps = Vs + 64*68;          // [128][68]  (row, key)
    __shared__ int s_item;

    const int tid = threadIdx.x;
    const int tx  = tid & 15;
    const int ty  = tid >> 4;
    // per-thread staging coords (4 chunks of 16B)
    const int sr0 = tid >> 4;          // rows 0..15 (+16 per chunk)
    const int sc4 = (tid & 15) << 2;   // col group

    for (;;) {
        __syncthreads();             // previous item fully done
        if (tid == 0) s_item = atomicAdd(&g_counter, 1);
        __syncthreads();
        const int it = s_item;
        if (it >= N_ITEMS) return;

        const int qr = it / 24;      // 0..15
        const int qx = 15 - qr;      // longest first
        const int bh = it - qr * 24;
        const int qb  = qx * 128;
        const int off = bh * SEQ * HD;

        #pragma unroll
        for (int i = tid; i < 2048; i += 256) {
            const int r = i >> 4, c4 = (i & 15) << 2;
            *reinterpret_cast<float4*>(&Qs[r*68 + c4]) =
                *reinterpret_cast<const float4*>(g_Q + off + (qb + r)*64 + c4);
        }

        // prefetch K tile 0 into registers
        float4 kreg[4];
        #pragma unroll
        for (int j = 0; j < 4; j++) {
            const int r = sr0 + j*16;
            kreg[j] = *reinterpret_cast<const float4*>(g_K + off + r*64 + sc4);
        }

        float l_i[8];
        u64 acc[8][2];
        #pragma unroll
        for (int i = 0; i < 8; i++) {
            l_i[i] = 0.f;
            acc[i][0] = 0ull; acc[i][1] = 0ull;
        }

        const int nkt = 2*qx + 2;    // causal: keys up to qb+127
        for (int kt = 0; kt < nkt; ++kt) {
            const int kb = kt * 64;
            __syncthreads();         // prev PV done: Ks/Vs free
            // store prefetched K (transposed d-major)
            #pragma unroll
            for (int j = 0; j < 4; j++) {
                const int r = sr0 + j*16;
                Ks[(sc4+0)*68 + r] = kreg[j].x;
                Ks[(sc4+1)*68 + r] = kreg[j].y;
                Ks[(sc4+2)*68 + r] = kreg[j].z;
                Ks[(sc4+3)*68 + r] = kreg[j].w;
            }
            __syncthreads();         // Ks (and Qs on first tile) visible

            // prefetch next K tile into registers (lands during compute)
            if (kt + 1 < nkt) {
                const int kb2 = kb + 64;
                #pragma unroll
                for (int j = 0; j < 4; j++) {
                    const int r = sr0 + j*16;
                    kreg[j] = *reinterpret_cast<const float4*>(
                        g_K + off + (kb2 + r)*64 + sc4);
                }
            }
            // async-copy current V tile (covered by QK compute below)
            #pragma unroll
            for (int j = 0; j < 4; j++) {
                const int r = sr0 + j*16;
                cp16(&Vs[r*68 + sc4], g_V + off + (kb + r)*64 + sc4);
            }
            cp_commit();

            // ---- S = Q @ K^T  (8 rows x 2 f32x2-pairs per thread) ----
            u64 s2[8][2];
            #pragma unroll
            for (int i = 0; i < 8; i++) { s2[i][0] = 0ull; s2[i][1] = 0ull; }

            #pragma unroll 4
            for (int kk = 0; kk < 64; kk += 4) {
                ulonglong2 b0 = *reinterpret_cast<const ulonglong2*>(&Ks[(kk+0)*68 + tx*4]);
                ulonglong2 b1 = *reinterpret_cast<const ulonglong2*>(&Ks[(kk+1)*68 + tx*4]);
                ulonglong2 b2 = *reinterpret_cast<const ulonglong2*>(&Ks[(kk+2)*68 + tx*4]);
                ulonglong2 b3 = *reinterpret_cast<const ulonglong2*>(&Ks[(kk+3)*68 + tx*4]);
                #pragma unroll
                for (int i = 0; i < 8; i++) {
                    float4 t = *reinterpret_cast<const float4*>(&Qs[(ty*8+i)*68 + kk]);
                    u64 a;
                    a = bc2(t.x); fma2(s2[i][0], a, b0.x); fma2(s2[i][1], a, b0.y);
                    a = bc2(t.y); fma2(s2[i][0], a, b1.x); fma2(s2[i][1], a, b1.y);
                    a = bc2(t.z); fma2(s2[i][0], a, b2.x); fma2(s2[i][1], a, b2.y);
                    a = bc2(t.w); fma2(s2[i][0], a, b3.x); fma2(s2[i][1], a, b3.y);
                }
            }

            // ---- mask + exp (fixed max = 0) + partial row sums + write P ----
            const int row0 = qb + ty*8;
            const int col0 = kb + tx*4;
            #pragma unroll
            for (int i = 0; i < 8; i++) {
                const int row = row0 + i;
                float2 u0 = unpk2(s2[i][0]);
                float2 u1 = unpk2(s2[i][1]);
                float s0 = u0.x, s1 = u0.y, s2v = u1.x, s3 = u1.y;
                if ((col0 + 0 > row) || (s0  == 0.0f)) s0  = NEGV;
                if ((col0 + 1 > row) || (s1  == 0.0f)) s1  = NEGV;
                if ((col0 + 2 > row) || (s2v == 0.0f)) s2v = NEGV;
                if ((col0 + 3 > row) || (s3  == 0.0f)) s3  = NEGV;
                const float p0 = __expf(s0);
                const float p1 = __expf(s1);
                const float p2 = __expf(s2v);
                const float p3 = __expf(s3);
                l_i[i] += (p0 + p1) + (p2 + p3);
                *reinterpret_cast<float4*>(&Ps[(ty*8+i)*68 + tx*4]) =
                    make_float4(p0, p1, p2, p3);
            }
            cp_wait0();              // V landed
            __syncthreads();         // Ps + Vs visible

            // ---- acc += P @ V ----
            #pragma unroll 4
            for (int kk = 0; kk < 64; kk += 4) {
                ulonglong2 b0 = *reinterpret_cast<const ulonglong2*>(&Vs[(kk+0)*68 + tx*4]);
                ulonglong2 b1 = *reinterpret_cast<const ulonglong2*>(&Vs[(kk+1)*68 + tx*4]);
                ulonglong2 b2 = *reinterpret_cast<const ulonglong2*>(&Vs[(kk+2)*68 + tx*4]);
                ulonglong2 b3 = *reinterpret_cast<const ulonglong2*>(&Vs[(kk+3)*68 + tx*4]);
                #pragma unroll
                for (int i = 0; i < 8; i++) {
                    float4 t = *reinterpret_cast<const float4*>(&Ps[(ty*8+i)*68 + kk]);
                    u64 a;
                    a = bc2(t.x); fma2(acc[i][0], a, b0.x); fma2(acc[i][1], a, b0.y);
                    a = bc2(t.y); fma2(acc[i][0], a, b1.x); fma2(acc[i][1], a, b1.y);
                    a = bc2(t.z); fma2(acc[i][0], a, b2.x); fma2(acc[i][1], a, b2.y);
                    a = bc2(t.w); fma2(acc[i][0], a, b3.x); fma2(acc[i][1], a, b3.y);
                }
            }
        }

        // ---- epilogue: reduce row sums across the 16 tx lanes, normalize ----
        #pragma unroll
        for (int i = 0; i < 8; i++) {
            float l = l_i[i];
            #pragma unroll
            for (int o_ = 8; o_; o_ >>= 1)
                l += __shfl_xor_sync(0xffffffffu, l, o_);
            const u64 inv2 = bc2(1.0f / l);
            mul2(acc[i][0], inv2);
            mul2(acc[i][1], inv2);
            ulonglong2 o; o.x = acc[i][0]; o.y = acc[i][1];
            *reinterpret_cast<ulonglong2*>(g_Oa + off + (qb + ty*8 + i)*64 + tx*4) = o;
        }
    }
}

// ---------------------------------------------------------------------------
// Kernel 3: output projection.  merge-heads(O)[4096,768] @ Wo[768,64] + bo.
// Block: 32 rows x 64 cols, K looped over 12 heads of 64.
// ---------------------------------------------------------------------------
__global__ __launch_bounds__(256) void proj_kernel(
    const float* __restrict__ Wo, const float* __restrict__ bo,
    float* __restrict__ out)
{
    __shared__ float As[32*68];
    __shared__ float Ws[64*68];
    const int blk = blockIdx.x;     // 0..127, 32 rows each
    const int tid = threadIdx.x;
    const int tx  = tid & 15;
    const int ty  = tid >> 4;

    u64 acc[2][2];
    #pragma unroll
    for (int i = 0; i < 2; i++) { acc[i][0] = 0ull; acc[i][1] = 0ull; }

    #pragma unroll 1
    for (int h = 0; h < NH; ++h) {
        __syncthreads();
        #pragma unroll
        for (int i = tid; i < 512; i += 256) {
            const int r = i >> 4, c4 = (i & 15) << 2;
            const int rg = blk*32 + r;
            const int bi = rg >> 11;
            const int si = rg & (SEQ-1);
            *reinterpret_cast<float4*>(&As[r*68 + c4]) =
                *reinterpret_cast<const float4*>(g_Oa + ((bi*NH + h)*SEQ + si)*HD + c4);
        }
        #pragma unroll
        for (int i = tid; i < 1024; i += 256) {
            const int k = i >> 4, c4 = (i & 15) << 2;
            *reinterpret_cast<float4*>(&Ws[k*68 + c4]) =
                *reinterpret_cast<const float4*>(Wo + (h*64 + k)*64 + c4);
        }
        __syncthreads();

        #pragma unroll 4
        for (int kk = 0; kk < 64; kk += 4) {
            ulonglong2 b0 = *reinterpret_cast<const ulonglong2*>(&Ws[(kk+0)*68 + tx*4]);
            ulonglong2 b1 = *reinterpret_cast<const ulonglong2*>(&Ws[(kk+1)*68 + tx*4]);
            ulonglong2 b2 = *reinterpret_cast<const ulonglong2*>(&Ws[(kk+2)*68 + tx*4]);
            ulonglong2 b3 = *reinterpret_cast<const ulonglong2*>(&Ws[(kk+3)*68 + tx*4]);
            #pragma unroll
            for (int i = 0; i < 2; i++) {
                float4 t = *reinterpret_cast<const float4*>(&As[(ty*2+i)*68 + kk]);
                u64 a;
                a = bc2(t.x); fma2(acc[i][0], a, b0.x); fma2(acc[i][1], a, b0.y);
                a = bc2(t.y); fma2(acc[i][0], a, b1.x); fma2(acc[i][1], a, b1.y);
                a = bc2(t.z); fma2(acc[i][0], a, b2.x); fma2(acc[i][1], a, b2.y);
                a = bc2(t.w); fma2(acc[i][0], a, b3.x); fma2(acc[i][1], a, b3.y);
            }
        }
    }

    const ulonglong2 bias = *reinterpret_cast<const ulonglong2*>(bo + tx*4);
    #pragma unroll
    for (int i = 0; i < 2; i++) {
        const int rg = blk*32 + ty*2 + i;
        add2(acc[i][0], bias.x);
        add2(acc[i][1], bias.y);
        ulonglong2 o; o.x = acc[i][0]; o.y = acc[i][1];
        *reinterpret_cast<ulonglong2*>(out + rg*64 + tx*4) = o;
    }
}

// ---------------------------------------------------------------------------
extern "C" void kernel_launch(void* const* d_in, const int* in_sizes, int n_in,
                              void* d_out, int out_size)
{
    (void)in_sizes; (void)n_in; (void)out_size;
    const float* x  = (const float*)d_in[0];
    const float* Wq = (const float*)d_in[1];
    const float* bq = (const float*)d_in[2];
    const float* Wk = (const float*)d_in[3];
    const float* bk = (const float*)d_in[4];
    const float* Wv = (const float*)d_in[5];
    const float* bv = (const float*)d_in[6];
    const float* Wo = (const float*)d_in[7];
    const float* bo = (const float*)d_in[8];
    float* out = (float*)d_out;

    cudaFuncSetAttribute(attn_kernel,
                         cudaFuncAttributeMaxDynamicSharedMemorySize,
                         ATTN_SMEM_BYTES);
    cudaFuncSetAttribute(qkv_kernel,
                         cudaFuncAttributeMaxDynamicSharedMemorySize,
                         QKV_SMEM_BYTES);

    reset_counter<<<1, 1>>>();
    qkv_kernel<<<dim3(64, 12), 256, QKV_SMEM_BYTES>>>(x, Wq, bq, Wk, bk, Wv, bv);
    attn_kernel<<<N_CTAS, 256, ATTN_SMEM_BYTES>>>();
    proj_kernel<<<128, 256>>>(Wo, bo, out);
}

// round 8
// speedup vs baseline: 2.4002x; 2.3969x over previous
#include <cuda_runtime.h>
#include <cuda_bf16.h>
#include <cstdint>

#define NUM_B 2
#define SEQ   2048
#define HD    64
#define NH    12
#define NEGV  (-99999.0f)
#define TOT   (NUM_B*NH*SEQ*HD)
#define N_ITEMS (16*24)
#define N_CTAS  296

typedef unsigned long long u64;

// ---- packed f32x2 (qkv/proj fp32 paths) ----
__device__ __forceinline__ u64 bc2(float x) {
    u64 r; asm("mov.b64 %0, {%1, %1};" : "=l"(r) : "f"(x)); return r;
}
__device__ __forceinline__ void fma2(u64 &d, u64 a, u64 b) {
    asm("fma.rn.f32x2 %0, %1, %2, %0;" : "+l"(d) : "l"(a), "l"(b));
}
__device__ __forceinline__ void add2(u64 &d, u64 a) {
    asm("add.rn.f32x2 %0, %0, %1;" : "+l"(d) : "l"(a));
}
__device__ __forceinline__ float2 unpk2(u64 a) {
    float2 f; asm("mov.b64 {%0, %1}, %2;" : "=f"(f.x), "=f"(f.y) : "l"(a)); return f;
}

// ---- cp.async ----
__device__ __forceinline__ void cp16(void* smem_dst, const void* gmem_src) {
    unsigned s = (unsigned)__cvta_generic_to_shared(smem_dst);
    asm volatile("cp.async.ca.shared.global [%0], [%1], 16;\n" :: "r"(s), "l"(gmem_src));
}
__device__ __forceinline__ void cp_commit() { asm volatile("cp.async.commit_group;\n"); }
__device__ __forceinline__ void cp_wait0()  { asm volatile("cp.async.wait_group 0;\n" ::: "memory"); }

__device__ __forceinline__ uint32_t smem_u32(const void* p) {
    uint32_t a;
    asm("{ .reg .u64 t; cvta.to.shared.u64 t, %1; cvt.u32.u64 %0, t; }" : "=r"(a) : "l"(p));
    return a;
}

// ---- warp MMA primitives (baseline PTX, works at compute_103) ----
__device__ __forceinline__ void mma16816(float* d, const uint32_t* a, uint32_t b0, uint32_t b1) {
    asm volatile("mma.sync.aligned.m16n8k16.row.col.f32.bf16.bf16.f32 "
                 "{%0,%1,%2,%3}, {%4,%5,%6,%7}, {%8,%9}, {%0,%1,%2,%3};"
                 : "+f"(d[0]), "+f"(d[1]), "+f"(d[2]), "+f"(d[3])
                 : "r"(a[0]), "r"(a[1]), "r"(a[2]), "r"(a[3]), "r"(b0), "r"(b1));
}
__device__ __forceinline__ void ldx4(uint32_t* r, uint32_t addr) {
    asm volatile("ldmatrix.sync.aligned.m8n8.x4.shared.b16 {%0,%1,%2,%3}, [%4];"
                 : "=r"(r[0]), "=r"(r[1]), "=r"(r[2]), "=r"(r[3]) : "r"(addr));
}
__device__ __forceinline__ void ldx4t(uint32_t* r, uint32_t addr) {
    asm volatile("ldmatrix.sync.aligned.m8n8.x4.trans.shared.b16 {%0,%1,%2,%3}, [%4];"
                 : "=r"(r[0]), "=r"(r[1]), "=r"(r[2]), "=r"(r[3]) : "r"(addr));
}

__device__ __forceinline__ uint32_t packbf2(__nv_bfloat16 a, __nv_bfloat16 b) {
    __nv_bfloat162 t; t.x = a; t.y = b; return *reinterpret_cast<uint32_t*>(&t);
}
__device__ __forceinline__ uint32_t pack_hi(float a, float b) {
    return packbf2(__float2bfloat16_rn(a), __float2bfloat16_rn(b));
}
__device__ __forceinline__ uint32_t pack_lo(float a, float b, uint32_t hi) {
    __nv_bfloat162 h = *reinterpret_cast<__nv_bfloat162*>(&hi);
    return packbf2(__float2bfloat16_rn(a - __bfloat162float(h.x)),
                   __float2bfloat16_rn(b - __bfloat162float(h.y)));
}

// ---- global scratch (all [bh][s][d]) ----
__device__ __align__(16) __nv_bfloat16 g_Qh[TOT];
__device__ __align__(16) __nv_bfloat16 g_Ql[TOT];
__device__ __align__(16) __nv_bfloat16 g_Kh[TOT];
__device__ __align__(16) __nv_bfloat16 g_Kl[TOT];
__device__ __align__(16) __nv_bfloat16 g_Vh[TOT];
__device__ __align__(16) __nv_bfloat16 g_Vl[TOT];
__device__ float g_Oa[TOT];
__device__ int   g_counter;

__global__ void reset_counter() { g_counter = 0; }

// ---------------------------------------------------------------------------
// Kernel 1: fused QKV projection (fp32 FFMA2) -> bf16 hi/lo globals.
// ---------------------------------------------------------------------------
#define QKV_SMEM_BYTES (4*64*68*4)

__global__ __launch_bounds__(256) void qkv_kernel(
    const float* __restrict__ x,
    const float* __restrict__ Wq, const float* __restrict__ bq,
    const float* __restrict__ Wk, const float* __restrict__ bk,
    const float* __restrict__ Wv, const float* __restrict__ bv)
{
    extern __shared__ float smq[];
    float* xs  = smq;
    float* ws0 = xs  + 64*68;
    float* ws1 = ws0 + 64*68;
    float* ws2 = ws1 + 64*68;
    const int tile = blockIdx.x;
    const int head = blockIdx.y;
    const int tid  = threadIdx.x;
    const int tx   = tid & 15;
    const int ty   = tid >> 4;

    #pragma unroll
    for (int i = tid; i < 1024; i += 256) {
        const int r = i >> 4, c4 = (i & 15) << 2;
        *reinterpret_cast<float4*>(&xs[r*68 + c4]) =
            *reinterpret_cast<const float4*>(x + (tile*64 + r)*64 + c4);
        *reinterpret_cast<float4*>(&ws0[r*68 + c4]) =
            *reinterpret_cast<const float4*>(Wq + r*768 + head*64 + c4);
        *reinterpret_cast<float4*>(&ws1[r*68 + c4]) =
            *reinterpret_cast<const float4*>(Wk + r*768 + head*64 + c4);
        *reinterpret_cast<float4*>(&ws2[r*68 + c4]) =
            *reinterpret_cast<const float4*>(Wv + r*768 + head*64 + c4);
    }
    __syncthreads();

    u64 acc[3][4][2];
    #pragma unroll
    for (int m = 0; m < 3; m++)
        #pragma unroll
        for (int i = 0; i < 4; i++) { acc[m][i][0] = 0ull; acc[m][i][1] = 0ull; }

    #pragma unroll 4
    for (int kk = 0; kk < 64; kk += 4) {
        u64 ax[4][4];
        #pragma unroll
        for (int i = 0; i < 4; i++) {
            float4 t = *reinterpret_cast<const float4*>(&xs[(ty*4+i)*68 + kk]);
            ax[i][0] = bc2(t.x); ax[i][1] = bc2(t.y);
            ax[i][2] = bc2(t.z); ax[i][3] = bc2(t.w);
        }
        const float* wsm[3] = {ws0, ws1, ws2};
        #pragma unroll
        for (int m = 0; m < 3; m++) {
            const float* w = wsm[m];
            ulonglong2 b0 = *reinterpret_cast<const ulonglong2*>(&w[(kk+0)*68 + tx*4]);
            ulonglong2 b1 = *reinterpret_cast<const ulonglong2*>(&w[(kk+1)*68 + tx*4]);
            ulonglong2 b2 = *reinterpret_cast<const ulonglong2*>(&w[(kk+2)*68 + tx*4]);
            ulonglong2 b3 = *reinterpret_cast<const ulonglong2*>(&w[(kk+3)*68 + tx*4]);
            #pragma unroll
            for (int i = 0; i < 4; i++) {
                fma2(acc[m][i][0], ax[i][0], b0.x); fma2(acc[m][i][1], ax[i][0], b0.y);
                fma2(acc[m][i][0], ax[i][1], b1.x); fma2(acc[m][i][1], ax[i][1], b1.y);
                fma2(acc[m][i][0], ax[i][2], b2.x); fma2(acc[m][i][1], ax[i][2], b2.y);
                fma2(acc[m][i][0], ax[i][3], b3.x); fma2(acc[m][i][1], ax[i][3], b3.y);
            }
        }
    }

    const float* Bm[3] = {bq, bk, bv};
    __nv_bfloat16* const Hm[3] = {g_Qh, g_Kh, g_Vh};
    __nv_bfloat16* const Lm[3] = {g_Ql, g_Kl, g_Vl};
    const int rg0 = tile*64 + ty*4;
    const int bi  = rg0 >> 11;
    const int si0 = rg0 & (SEQ-1);
    const int bh  = bi*NH + head;

    #pragma unroll
    for (int m = 0; m < 3; m++) {
        const ulonglong2 bias = *reinterpret_cast<const ulonglong2*>(Bm[m] + head*64 + tx*4);
        #pragma unroll
        for (int i = 0; i < 4; i++) {
            add2(acc[m][i][0], bias.x);
            add2(acc[m][i][1], bias.y);
            float2 f0 = unpk2(acc[m][i][0]), f1 = unpk2(acc[m][i][1]);
            uint32_t h0 = pack_hi(f0.x, f0.y);
            uint32_t h1 = pack_hi(f1.x, f1.y);
            uint32_t l0 = pack_lo(f0.x, f0.y, h0);
            uint32_t l1 = pack_lo(f1.x, f1.y, h1);
            const int idx = (bh*SEQ + si0 + i)*HD + tx*4;
            *reinterpret_cast<uint2*>(Hm[m] + idx) = make_uint2(h0, h1);
            *reinterpret_cast<uint2*>(Lm[m] + idx) = make_uint2(l0, l1);
        }
    }
}

// ---------------------------------------------------------------------------
// Kernel 2: HMMA (mma.sync bf16-split) flash attention, fixed-max softmax,
// persistent queue, cp.async double-buffered K/V.  8 warps x 16 q-rows.
// Quirky mask: col>row OR score==0 -> NEG.
// ---------------------------------------------------------------------------
#define STRB    144                     // bytes per padded row (64 bf16 + 8 pad)
#define SM_ITEM 0
#define SM_QH   16
#define SM_QL   (SM_QH + 128*STRB)
#define SM_KH0  (SM_QL + 128*STRB)
#define SM_KL0  (SM_KH0 + 64*STRB)
#define SM_VH0  (SM_KL0 + 64*STRB)
#define SM_VL0  (SM_VH0 + 64*STRB)
#define SM_KH1  (SM_VL0 + 64*STRB)
#define SM_KL1  (SM_KH1 + 64*STRB)
#define SM_VH1  (SM_KL1 + 64*STRB)
#define SM_VL1  (SM_VH1 + 64*STRB)
#define ATTN_SMEM_BYTES (SM_VL1 + 64*STRB)

__global__ __launch_bounds__(256, 2) void attn_kernel()
{
    extern __shared__ __align__(16) char smn[];
    const uint32_t sb = smem_u32(smn);
    const int tid  = threadIdx.x;
    const int wid  = tid >> 5;           // warp = 16 q-rows
    const int lane = tid & 31;
    const int g    = lane >> 2;          // quad group (row within 8)
    const int t    = lane & 3;           // quad thread (col pair)
    int* itp = reinterpret_cast<int*>(smn + SM_ITEM);

    // ldmatrix per-lane address components
    const int qrow_l = (lane & 15);
    const int qch    = (lane >> 4);              // k half for A frags
    const int krow_l = ((lane >> 4) & 1)*8 + (lane & 7);
    const int kch    = (lane >> 3) & 1;
    const int vrow_l = ((lane >> 3) & 1)*8 + (lane & 7);
    const int vch    = (lane >> 4) & 1;

    for (;;) {
        __syncthreads();
        if (tid == 0) *itp = atomicAdd(&g_counter, 1);
        __syncthreads();
        const int it = *itp;
        if (it >= N_ITEMS) return;

        const int qr = it / 24;
        const int qx = 15 - qr;          // longest first
        const int bh = it - qr * 24;
        const int qb  = qx * 128;
        const int off = bh * SEQ * HD;

        // stage Q hi/lo (128 rows x 8 chunks of 16B)
        #pragma unroll
        for (int i = tid; i < 1024; i += 256) {
            const int r = i >> 3, c = i & 7;
            cp16(smn + SM_QH + r*STRB + c*16, g_Qh + off + (qb + r)*64 + c*8);
            cp16(smn + SM_QL + r*STRB + c*16, g_Ql + off + (qb + r)*64 + c*8);
        }
        // stage K/V tile 0 into buffer 0
        #pragma unroll
        for (int i = tid; i < 512; i += 256) {
            const int r = i >> 3, c = i & 7;
            cp16(smn + SM_KH0 + r*STRB + c*16, g_Kh + off + r*64 + c*8);
            cp16(smn + SM_KL0 + r*STRB + c*16, g_Kl + off + r*64 + c*8);
            cp16(smn + SM_VH0 + r*STRB + c*16, g_Vh + off + r*64 + c*8);
            cp16(smn + SM_VL0 + r*STRB + c*16, g_Vl + off + r*64 + c*8);
        }
        cp_commit();

        float dacc[8][4];
        #pragma unroll
        for (int j = 0; j < 8; j++)
            #pragma unroll
            for (int e = 0; e < 4; e++) dacc[j][e] = 0.f;
        float lsum0 = 0.f, lsum8 = 0.f;

        const int row0 = qb + wid*16 + g;
        const int row8 = row0 + 8;

        const int nkt = 2*qx + 2;
        for (int kt = 0; kt < nkt; ++kt) {
            const int kb  = kt * 64;
            const int buf = kt & 1;
            cp_wait0();
            __syncthreads();

            // prefetch next tile into other buffer
            if (kt + 1 < nkt) {
                const int nkb = kb + 64;
                const uint32_t okh = buf ? SM_KH0 : SM_KH1;
                const uint32_t okl = buf ? SM_KL0 : SM_KL1;
                const uint32_t ovh = buf ? SM_VH0 : SM_VH1;
                const uint32_t ovl = buf ? SM_VL0 : SM_VL1;
                #pragma unroll
                for (int i = tid; i < 512; i += 256) {
                    const int r = i >> 3, c = i & 7;
                    cp16(smn + okh + r*STRB + c*16, g_Kh + off + (nkb + r)*64 + c*8);
                    cp16(smn + okl + r*STRB + c*16, g_Kl + off + (nkb + r)*64 + c*8);
                    cp16(smn + ovh + r*STRB + c*16, g_Vh + off + (nkb + r)*64 + c*8);
                    cp16(smn + ovl + r*STRB + c*16, g_Vl + off + (nkb + r)*64 + c*8);
                }
            }
            cp_commit();

            const uint32_t bkh = sb + (buf ? SM_KH1 : SM_KH0);
            const uint32_t bkl = sb + (buf ? SM_KL1 : SM_KL0);
            const uint32_t bvh = sb + (buf ? SM_VH1 : SM_VH0);
            const uint32_t bvl = sb + (buf ? SM_VL1 : SM_VL0);

            // ---- S = Q @ K^T  (bf16-split: qh*kh + qh*kl + ql*kh) ----
            float sacc[8][4];
            #pragma unroll
            for (int j = 0; j < 8; j++)
                #pragma unroll
                for (int e = 0; e < 4; e++) sacc[j][e] = 0.f;

            #pragma unroll
            for (int ks = 0; ks < 4; ks++) {
                uint32_t qh[4], ql[4];
                const uint32_t qoff = (uint32_t)((wid*16 + qrow_l)*STRB + (ks*16 + qch*8)*2);
                ldx4(qh, sb + SM_QH + qoff);
                ldx4(ql, sb + SM_QL + qoff);
                #pragma unroll
                for (int jp = 0; jp < 4; jp++) {
                    const uint32_t koff = (uint32_t)((jp*16 + krow_l)*STRB + (ks*16 + kch*8)*2);
                    uint32_t khb[4], klb[4];
                    ldx4(khb, bkh + koff);
                    ldx4(klb, bkl + koff);
                    mma16816(sacc[2*jp],   qh, khb[0], khb[1]);
                    mma16816(sacc[2*jp+1], qh, khb[2], khb[3]);
                    mma16816(sacc[2*jp],   qh, klb[0], klb[1]);
                    mma16816(sacc[2*jp+1], qh, klb[2], klb[3]);
                    mma16816(sacc[2*jp],   ql, khb[0], khb[1]);
                    mma16816(sacc[2*jp+1], ql, khb[2], khb[3]);
                }
            }

            // ---- mask + exp(fixed max=0) + convert to P A-fragments ----
            uint32_t ph[4][4], pl[4][4];
            #pragma unroll
            for (int jn = 0; jn < 8; jn++) {
                const int col = kb + jn*8 + 2*t;
                float v0 = sacc[jn][0], v1 = sacc[jn][1];
                float v2 = sacc[jn][2], v3 = sacc[jn][3];
                if (col     > row0 || v0 == 0.0f) v0 = NEGV;
                if (col + 1 > row0 || v1 == 0.0f) v1 = NEGV;
                if (col     > row8 || v2 == 0.0f) v2 = NEGV;
                if (col + 1 > row8 || v3 == 0.0f) v3 = NEGV;
                const float p0 = __expf(v0);
                const float p1 = __expf(v1);
                const float p2 = __expf(v2);
                const float p3 = __expf(v3);
                lsum0 += p0 + p1;
                lsum8 += p2 + p3;
                const int kc = jn >> 1, half = jn & 1;
                uint32_t h01 = pack_hi(p0, p1);
                uint32_t h23 = pack_hi(p2, p3);
                ph[kc][half*2 + 0] = h01;
                ph[kc][half*2 + 1] = h23;
                pl[kc][half*2 + 0] = pack_lo(p0, p1, h01);
                pl[kc][half*2 + 1] = pack_lo(p2, p3, h23);
            }

            // ---- D += P @ V  (ph*vh + ph*vl + pl*vh) ----
            #pragma unroll
            for (int kc = 0; kc < 4; kc++) {
                #pragma unroll
                for (int jdp = 0; jdp < 4; jdp++) {
                    const uint32_t voff =
                        (uint32_t)((kc*16 + vrow_l)*STRB + ((2*jdp + vch)*8)*2);
                    uint32_t vhb[4], vlb[4];
                    ldx4t(vhb, bvh + voff);
                    ldx4t(vlb, bvl + voff);
                    mma16816(dacc[2*jdp],   ph[kc], vhb[0], vhb[1]);
                    mma16816(dacc[2*jdp+1], ph[kc], vhb[2], vhb[3]);
                    mma16816(dacc[2*jdp],   ph[kc], vlb[0], vlb[1]);
                    mma16816(dacc[2*jdp+1], ph[kc], vlb[2], vlb[3]);
                    mma16816(dacc[2*jdp],   pl[kc], vhb[0], vhb[1]);
                    mma16816(dacc[2*jdp+1], pl[kc], vhb[2], vhb[3]);
                }
            }
        }

        // ---- epilogue: quad-reduce row sums, normalize, store ----
        #pragma unroll
        for (int o_ = 1; o_ < 4; o_ <<= 1) {
            lsum0 += __shfl_xor_sync(0xffffffffu, lsum0, o_);
            lsum8 += __shfl_xor_sync(0xffffffffu, lsum8, o_);
        }
        const float inv0 = 1.0f / lsum0;
        const float inv8 = 1.0f / lsum8;
        #pragma unroll
        for (int jd = 0; jd < 8; jd++) {
            const int col = jd*8 + 2*t;
            *reinterpret_cast<float2*>(g_Oa + off + row0*64 + col) =
                make_float2(dacc[jd][0]*inv0, dacc[jd][1]*inv0);
            *reinterpret_cast<float2*>(g_Oa + off + row8*64 + col) =
                make_float2(dacc[jd][2]*inv8, dacc[jd][3]*inv8);
        }
        lsum0 = 0.f; lsum8 = 0.f;
    }
}

// ---------------------------------------------------------------------------
// Kernel 3: output projection (fp32 FFMA2, R4 structure).
// ---------------------------------------------------------------------------
__global__ __launch_bounds__(256) void proj_kernel(
    const float* __restrict__ Wo, const float* __restrict__ bo,
    float* __restrict__ out)
{
    __shared__ float As[32*68];
    __shared__ float Ws[64*68];
    const int blk = blockIdx.x;
    const int tid = threadIdx.x;
    const int tx  = tid & 15;
    const int ty  = tid >> 4;

    u64 acc[2][2];
    #pragma unroll
    for (int i = 0; i < 2; i++) { acc[i][0] = 0ull; acc[i][1] = 0ull; }

    #pragma unroll 1
    for (int h = 0; h < NH; ++h) {
        __syncthreads();
        #pragma unroll
        for (int i = tid; i < 512; i += 256) {
            const int r = i >> 4, c4 = (i & 15) << 2;
            const int rg = blk*32 + r;
            const int bi = rg >> 11;
            const int si = rg & (SEQ-1);
            *reinterpret_cast<float4*>(&As[r*68 + c4]) =
                *reinterpret_cast<const float4*>(g_Oa + ((bi*NH + h)*SEQ + si)*HD + c4);
        }
        #pragma unroll
        for (int i = tid; i < 1024; i += 256) {
            const int k = i >> 4, c4 = (i & 15) << 2;
            *reinterpret_cast<float4*>(&Ws[k*68 + c4]) =
                *reinterpret_cast<const float4*>(Wo + (h*64 + k)*64 + c4);
        }
        __syncthreads();

        #pragma unroll 4
        for (int kk = 0; kk < 64; kk += 4) {
            ulonglong2 b0 = *reinterpret_cast<const ulonglong2*>(&Ws[(kk+0)*68 + tx*4]);
            ulonglong2 b1 = *reinterpret_cast<const ulonglong2*>(&Ws[(kk+1)*68 + tx*4]);
            ulonglong2 b2 = *reinterpret_cast<const ulonglong2*>(&Ws[(kk+2)*68 + tx*4]);
            ulonglong2 b3 = *reinterpret_cast<const ulonglong2*>(&Ws[(kk+3)*68 + tx*4]);
            #pragma unroll
            for (int i = 0; i < 2; i++) {
                float4 tv = *reinterpret_cast<const float4*>(&As[(ty*2+i)*68 + kk]);
                u64 a;
                a = bc2(tv.x); fma2(acc[i][0], a, b0.x); fma2(acc[i][1], a, b0.y);
                a = bc2(tv.y); fma2(acc[i][0], a, b1.x); fma2(acc[i][1], a, b1.y);
                a = bc2(tv.z); fma2(acc[i][0], a, b2.x); fma2(acc[i][1], a, b2.y);
                a = bc2(tv.w); fma2(acc[i][0], a, b3.x); fma2(acc[i][1], a, b3.y);
            }
        }
    }

    const ulonglong2 bias = *reinterpret_cast<const ulonglong2*>(bo + tx*4);
    #pragma unroll
    for (int i = 0; i < 2; i++) {
        const int rg = blk*32 + ty*2 + i;
        add2(acc[i][0], bias.x);
        add2(acc[i][1], bias.y);
        ulonglong2 o; o.x = acc[i][0]; o.y = acc[i][1];
        *reinterpret_cast<ulonglong2*>(out + rg*64 + tx*4) = o;
    }
}

// ---------------------------------------------------------------------------
extern "C" void kernel_launch(void* const* d_in, const int* in_sizes, int n_in,
                              void* d_out, int out_size)
{
    (void)in_sizes; (void)n_in; (void)out_size;
    const float* x  = (const float*)d_in[0];
    const float* Wq = (const float*)d_in[1];
    const float* bq = (const float*)d_in[2];
    const float* Wk = (const float*)d_in[3];
    const float* bk = (const float*)d_in[4];
    const float* Wv = (const float*)d_in[5];
    const float* bv = (const float*)d_in[6];
    const float* Wo = (const float*)d_in[7];
    const float* bo = (const float*)d_in[8];
    float* out = (float*)d_out;

    cudaFuncSetAttribute(attn_kernel,
                         cudaFuncAttributeMaxDynamicSharedMemorySize,
                         ATTN_SMEM_BYTES);
    cudaFuncSetAttribute(qkv_kernel,
                         cudaFuncAttributeMaxDynamicSharedMemorySize,
                         QKV_SMEM_BYTES);

    reset_counter<<<1, 1>>>();
    qkv_kernel<<<dim3(64, 12), 256, QKV_SMEM_BYTES>>>(x, Wq, bq, Wk, bk, Wv, bv);
    attn_kernel<<<N_CTAS, 256, ATTN_SMEM_BYTES>>>();
    proj_kernel<<<128, 256>>>(Wo, bo, out);
}

// round 9
// speedup vs baseline: 2.6166x; 1.0901x over previous
#include <cuda_runtime.h>
#include <cuda_bf16.h>
#include <cstdint>

#define NUM_B 2
#define SEQ   2048
#define HD    64
#define NH    12
#define NEGV  (-99999.0f)
#define TOT   (NUM_B*NH*SEQ*HD)
#define N_ITEMS (16*24)
#define N_CTAS  296

// ---- cp.async ----
__device__ __forceinline__ void cp16(void* smem_dst, const void* gmem_src) {
    unsigned s = (unsigned)__cvta_generic_to_shared(smem_dst);
    asm volatile("cp.async.ca.shared.global [%0], [%1], 16;\n" :: "r"(s), "l"(gmem_src));
}
__device__ __forceinline__ void cp_commit() { asm volatile("cp.async.commit_group;\n"); }
__device__ __forceinline__ void cp_wait0()  { asm volatile("cp.async.wait_group 0;\n" ::: "memory"); }

__device__ __forceinline__ uint32_t smem_u32(const void* p) {
    uint32_t a;
    asm("{ .reg .u64 t; cvta.to.shared.u64 t, %1; cvt.u32.u64 %0, t; }" : "=r"(a) : "l"(p));
    return a;
}

// ---- warp MMA primitives ----
__device__ __forceinline__ void mma16816(float* d, const uint32_t* a, uint32_t b0, uint32_t b1) {
    asm volatile("mma.sync.aligned.m16n8k16.row.col.f32.bf16.bf16.f32 "
                 "{%0,%1,%2,%3}, {%4,%5,%6,%7}, {%8,%9}, {%0,%1,%2,%3};"
                 : "+f"(d[0]), "+f"(d[1]), "+f"(d[2]), "+f"(d[3])
                 : "r"(a[0]), "r"(a[1]), "r"(a[2]), "r"(a[3]), "r"(b0), "r"(b1));
}
__device__ __forceinline__ void ldx4(uint32_t* r, uint32_t addr) {
    asm volatile("ldmatrix.sync.aligned.m8n8.x4.shared.b16 {%0,%1,%2,%3}, [%4];"
                 : "=r"(r[0]), "=r"(r[1]), "=r"(r[2]), "=r"(r[3]) : "r"(addr));
}
__device__ __forceinline__ void ldx4t(uint32_t* r, uint32_t addr) {
    asm volatile("ldmatrix.sync.aligned.m8n8.x4.trans.shared.b16 {%0,%1,%2,%3}, [%4];"
                 : "=r"(r[0]), "=r"(r[1]), "=r"(r[2]), "=r"(r[3]) : "r"(addr));
}

__device__ __forceinline__ uint32_t packbf2(__nv_bfloat16 a, __nv_bfloat16 b) {
    __nv_bfloat162 t; t.x = a; t.y = b; return *reinterpret_cast<uint32_t*>(&t);
}
__device__ __forceinline__ uint32_t pack_hi(float a, float b) {
    return packbf2(__float2bfloat16_rn(a), __float2bfloat16_rn(b));
}
__device__ __forceinline__ uint32_t pack_lo(float a, float b, uint32_t hi) {
    __nv_bfloat162 h = *reinterpret_cast<__nv_bfloat162*>(&hi);
    return packbf2(__float2bfloat16_rn(a - __bfloat162float(h.x)),
                   __float2bfloat16_rn(b - __bfloat162float(h.y)));
}

// ---- global scratch ----
__device__ __align__(16) __nv_bfloat16 g_Qh[TOT];
__device__ __align__(16) __nv_bfloat16 g_Ql[TOT];
__device__ __align__(16) __nv_bfloat16 g_Kh[TOT];
__device__ __align__(16) __nv_bfloat16 g_Kl[TOT];
__device__ __align__(16) __nv_bfloat16 g_Vh[TOT];
__device__ __align__(16) __nv_bfloat16 g_Vl[TOT];
__device__ __align__(16) __nv_bfloat16 g_Ohi[TOT];
__device__ __align__(16) __nv_bfloat16 g_Olo[TOT];
__device__ __align__(16) __nv_bfloat16 g_Woh[768*64];
__device__ __align__(16) __nv_bfloat16 g_Wol[768*64];
__device__ int g_counter;

#define STRB 144   // bf16 row stride bytes (64 vals + pad)

// ---------------------------------------------------------------------------
// Kernel 0: prep — split Wo into bf16 hi/lo, reset work counter.
// ---------------------------------------------------------------------------
__global__ __launch_bounds__(256) void prep_kernel(const float* __restrict__ Wo)
{
    const int i = blockIdx.x*256 + threadIdx.x;   // 0..12287 float4 groups
    if (i == 0) g_counter = 0;
    float4 v = reinterpret_cast<const float4*>(Wo)[i];
    uint32_t h01 = pack_hi(v.x, v.y), h23 = pack_hi(v.z, v.w);
    uint32_t l01 = pack_lo(v.x, v.y, h01), l23 = pack_lo(v.z, v.w, h23);
    *reinterpret_cast<uint2*>(g_Woh + i*4) = make_uint2(h01, h23);
    *reinterpret_cast<uint2*>(g_Wol + i*4) = make_uint2(l01, l23);
}

// ---------------------------------------------------------------------------
// Kernel 1: HMMA fused QKV projection.  CTA = 64 rows x one head, 4 warps.
// x,W converted to bf16 hi/lo in smem; 3-term split GEMM; outputs hi/lo.
// ---------------------------------------------------------------------------
#define QK2_XH 0
#define QK2_XL (64*STRB)
#define QK2_WB (2*64*STRB)
#define QKV2_SMEM (QK2_WB + 6*64*STRB)   // 73728

__global__ __launch_bounds__(128) void qkv_kernel(
    const float* __restrict__ x,
    const float* __restrict__ Wq, const float* __restrict__ bq,
    const float* __restrict__ Wk, const float* __restrict__ bk,
    const float* __restrict__ Wv, const float* __restrict__ bv)
{
    extern __shared__ __align__(16) char smn[];
    const uint32_t sb = smem_u32(smn);
    const int tile = blockIdx.x;     // 0..63 (64 rows each)
    const int head = blockIdx.y;
    const int tid  = threadIdx.x;
    const int wid  = tid >> 5;       // 4 warps x 16 rows
    const int lane = tid & 31;
    const int g    = lane >> 2;
    const int t    = lane & 3;
    const int qrow_l = lane & 15;
    const int qch    = lane >> 4;
    const int vrow_l = ((lane >> 3) & 1)*8 + (lane & 7);
    const int vch    = (lane >> 4) & 1;

    // stage x (64x64 fp32 -> bf16 hi/lo)
    #pragma unroll
    for (int i = tid; i < 1024; i += 128) {
        const int r = i >> 4, c4 = (i & 15) << 2;
        float4 v = *reinterpret_cast<const float4*>(x + (tile*64 + r)*64 + c4);
        uint32_t h01 = pack_hi(v.x, v.y), h23 = pack_hi(v.z, v.w);
        uint32_t l01 = pack_lo(v.x, v.y, h01), l23 = pack_lo(v.z, v.w, h23);
        *reinterpret_cast<uint2*>(smn + QK2_XH + r*STRB + c4*2) = make_uint2(h01, h23);
        *reinterpret_cast<uint2*>(smn + QK2_XL + r*STRB + c4*2) = make_uint2(l01, l23);
    }
    // stage W tiles (3 x 64x64)
    {
        const float* const Wm[3] = {Wq, Wk, Wv};
        #pragma unroll
        for (int m = 0; m < 3; m++) {
            const float* W = Wm[m];
            const int base = QK2_WB + m*(2*64*STRB);
            #pragma unroll
            for (int i = tid; i < 1024; i += 128) {
                const int r = i >> 4, c4 = (i & 15) << 2;
                float4 v = *reinterpret_cast<const float4*>(W + r*768 + head*64 + c4);
                uint32_t h01 = pack_hi(v.x, v.y), h23 = pack_hi(v.z, v.w);
                uint32_t l01 = pack_lo(v.x, v.y, h01), l23 = pack_lo(v.z, v.w, h23);
                *reinterpret_cast<uint2*>(smn + base + r*STRB + c4*2) = make_uint2(h01, h23);
                *reinterpret_cast<uint2*>(smn + base + 64*STRB + r*STRB + c4*2) = make_uint2(l01, l23);
            }
        }
    }
    __syncthreads();

    // A fragments for x (shared across Q/K/V)
    uint32_t ah[4][4], al[4][4];
    #pragma unroll
    for (int kc = 0; kc < 4; kc++) {
        const uint32_t aoff = (uint32_t)((wid*16 + qrow_l)*STRB + (kc*16 + qch*8)*2);
        ldx4(ah[kc], sb + QK2_XH + aoff);
        ldx4(al[kc], sb + QK2_XL + aoff);
    }

    const int rg0 = tile*64 + wid*16 + g;
    const int bi  = rg0 >> 11;
    const int si0 = rg0 & (SEQ-1);
    const int bh  = bi*NH + head;
    const float* const Bm[3] = {bq, bk, bv};
    __nv_bfloat16* const Hm[3] = {g_Qh, g_Kh, g_Vh};
    __nv_bfloat16* const Lm[3] = {g_Ql, g_Kl, g_Vl};

    #pragma unroll
    for (int m = 0; m < 3; m++) {
        const uint32_t whb = sb + QK2_WB + m*(2*64*STRB);
        const uint32_t wlb = whb + 64*STRB;
        float dacc[8][4];
        #pragma unroll
        for (int j = 0; j < 8; j++)
            #pragma unroll
            for (int e = 0; e < 4; e++) dacc[j][e] = 0.f;

        #pragma unroll
        for (int kc = 0; kc < 4; kc++) {
            #pragma unroll
            for (int jdp = 0; jdp < 4; jdp++) {
                const uint32_t voff = (uint32_t)((kc*16 + vrow_l)*STRB + ((2*jdp + vch)*8)*2);
                uint32_t bhf[4], blf[4];
                ldx4t(bhf, whb + voff);
                ldx4t(blf, wlb + voff);
                mma16816(dacc[2*jdp],   ah[kc], bhf[0], bhf[1]);
                mma16816(dacc[2*jdp+1], ah[kc], bhf[2], bhf[3]);
                mma16816(dacc[2*jdp],   ah[kc], blf[0], blf[1]);
                mma16816(dacc[2*jdp+1], ah[kc], blf[2], blf[3]);
                mma16816(dacc[2*jdp],   al[kc], bhf[0], bhf[1]);
                mma16816(dacc[2*jdp+1], al[kc], bhf[2], bhf[3]);
            }
        }

        const float* bias = Bm[m] + head*64;
        __nv_bfloat16* H = Hm[m];
        __nv_bfloat16* L = Lm[m];
        #pragma unroll
        for (int jd = 0; jd < 8; jd++) {
            const int col = jd*8 + 2*t;
            const float b0 = bias[col], b1 = bias[col+1];
            const float v0 = dacc[jd][0] + b0, v1 = dacc[jd][1] + b1;
            const float v2 = dacc[jd][2] + b0, v3 = dacc[jd][3] + b1;
            uint32_t h01 = pack_hi(v0, v1), l01 = pack_lo(v0, v1, h01);
            uint32_t h23 = pack_hi(v2, v3), l23 = pack_lo(v2, v3, h23);
            const int idx0 = (bh*SEQ + si0)*HD + col;
            const int idx8 = idx0 + 8*HD;
            *reinterpret_cast<uint32_t*>(H + idx0) = h01;
            *reinterpret_cast<uint32_t*>(L + idx0) = l01;
            *reinterpret_cast<uint32_t*>(H + idx8) = h23;
            *reinterpret_cast<uint32_t*>(L + idx8) = l23;
        }
    }
}

// ---------------------------------------------------------------------------
// Kernel 2: HMMA flash attention (unchanged from R8 except bf16 hi/lo output).
// ---------------------------------------------------------------------------
#define SM_ITEM 0
#define SM_QH   16
#define SM_QL   (SM_QH + 128*STRB)
#define SM_KH0  (SM_QL + 128*STRB)
#define SM_KL0  (SM_KH0 + 64*STRB)
#define SM_VH0  (SM_KL0 + 64*STRB)
#define SM_VL0  (SM_VH0 + 64*STRB)
#define SM_KH1  (SM_VL0 + 64*STRB)
#define SM_KL1  (SM_KH1 + 64*STRB)
#define SM_VH1  (SM_KL1 + 64*STRB)
#define SM_VL1  (SM_VH1 + 64*STRB)
#define ATTN_SMEM_BYTES (SM_VL1 + 64*STRB)

__global__ __launch_bounds__(256, 2) void attn_kernel()
{
    extern __shared__ __align__(16) char smn[];
    const uint32_t sb = smem_u32(smn);
    const int tid  = threadIdx.x;
    const int wid  = tid >> 5;
    const int lane = tid & 31;
    const int g    = lane >> 2;
    const int t    = lane & 3;
    int* itp = reinterpret_cast<int*>(smn + SM_ITEM);

    const int qrow_l = (lane & 15);
    const int qch    = (lane >> 4);
    const int krow_l = ((lane >> 4) & 1)*8 + (lane & 7);
    const int kch    = (lane >> 3) & 1;
    const int vrow_l = ((lane >> 3) & 1)*8 + (lane & 7);
    const int vch    = (lane >> 4) & 1;

    for (;;) {
        __syncthreads();
        if (tid == 0) *itp = atomicAdd(&g_counter, 1);
        __syncthreads();
        const int it = *itp;
        if (it >= N_ITEMS) return;

        const int qr = it / 24;
        const int qx = 15 - qr;
        const int bh = it - qr * 24;
        const int qb  = qx * 128;
        const int off = bh * SEQ * HD;

        #pragma unroll
        for (int i = tid; i < 1024; i += 256) {
            const int r = i >> 3, c = i & 7;
            cp16(smn + SM_QH + r*STRB + c*16, g_Qh + off + (qb + r)*64 + c*8);
            cp16(smn + SM_QL + r*STRB + c*16, g_Ql + off + (qb + r)*64 + c*8);
        }
        #pragma unroll
        for (int i = tid; i < 512; i += 256) {
            const int r = i >> 3, c = i & 7;
            cp16(smn + SM_KH0 + r*STRB + c*16, g_Kh + off + r*64 + c*8);
            cp16(smn + SM_KL0 + r*STRB + c*16, g_Kl + off + r*64 + c*8);
            cp16(smn + SM_VH0 + r*STRB + c*16, g_Vh + off + r*64 + c*8);
            cp16(smn + SM_VL0 + r*STRB + c*16, g_Vl + off + r*64 + c*8);
        }
        cp_commit();

        float dacc[8][4];
        #pragma unroll
        for (int j = 0; j < 8; j++)
            #pragma unroll
            for (int e = 0; e < 4; e++) dacc[j][e] = 0.f;
        float lsum0 = 0.f, lsum8 = 0.f;

        const int row0 = qb + wid*16 + g;
        const int row8 = row0 + 8;

        const int nkt = 2*qx + 2;
        for (int kt = 0; kt < nkt; ++kt) {
            const int kb  = kt * 64;
            const int buf = kt & 1;
            cp_wait0();
            __syncthreads();

            if (kt + 1 < nkt) {
                const int nkb = kb + 64;
                const uint32_t okh = buf ? SM_KH0 : SM_KH1;
                const uint32_t okl = buf ? SM_KL0 : SM_KL1;
                const uint32_t ovh = buf ? SM_VH0 : SM_VH1;
                const uint32_t ovl = buf ? SM_VL0 : SM_VL1;
                #pragma unroll
                for (int i = tid; i < 512; i += 256) {
                    const int r = i >> 3, c = i & 7;
                    cp16(smn + okh + r*STRB + c*16, g_Kh + off + (nkb + r)*64 + c*8);
                    cp16(smn + okl + r*STRB + c*16, g_Kl + off + (nkb + r)*64 + c*8);
                    cp16(smn + ovh + r*STRB + c*16, g_Vh + off + (nkb + r)*64 + c*8);
                    cp16(smn + ovl + r*STRB + c*16, g_Vl + off + (nkb + r)*64 + c*8);
                }
            }
            cp_commit();

            const uint32_t bkh = sb + (buf ? SM_KH1 : SM_KH0);
            const uint32_t bkl = sb + (buf ? SM_KL1 : SM_KL0);
            const uint32_t bvh = sb + (buf ? SM_VH1 : SM_VH0);
            const uint32_t bvl = sb + (buf ? SM_VL1 : SM_VL0);

            float sacc[8][4];
            #pragma unroll
            for (int j = 0; j < 8; j++)
                #pragma unroll
                for (int e = 0; e < 4; e++) sacc[j][e] = 0.f;

            #pragma unroll
            for (int ks = 0; ks < 4; ks++) {
                uint32_t qh[4], ql[4];
                const uint32_t qoff = (uint32_t)((wid*16 + qrow_l)*STRB + (ks*16 + qch*8)*2);
                ldx4(qh, sb + SM_QH + qoff);
                ldx4(ql, sb + SM_QL + qoff);
                #pragma unroll
                for (int jp = 0; jp < 4; jp++) {
                    const uint32_t koff = (uint32_t)((jp*16 + krow_l)*STRB + (ks*16 + kch*8)*2);
                    uint32_t khb[4], klb[4];
                    ldx4(khb, bkh + koff);
                    ldx4(klb, bkl + koff);
                    mma16816(sacc[2*jp],   qh, khb[0], khb[1]);
                    mma16816(sacc[2*jp+1], qh, khb[2], khb[3]);
                    mma16816(sacc[2*jp],   qh, klb[0], klb[1]);
                    mma16816(sacc[2*jp+1], qh, klb[2], klb[3]);
                    mma16816(sacc[2*jp],   ql, khb[0], khb[1]);
                    mma16816(sacc[2*jp+1], ql, khb[2], khb[3]);
                }
            }

            uint32_t ph[4][4], pl[4][4];
            #pragma unroll
            for (int jn = 0; jn < 8; jn++) {
                const int col = kb + jn*8 + 2*t;
                float v0 = sacc[jn][0], v1 = sacc[jn][1];
                float v2 = sacc[jn][2], v3 = sacc[jn][3];
                if (col     > row0 || v0 == 0.0f) v0 = NEGV;
                if (col + 1 > row0 || v1 == 0.0f) v1 = NEGV;
                if (col     > row8 || v2 == 0.0f) v2 = NEGV;
                if (col + 1 > row8 || v3 == 0.0f) v3 = NEGV;
                const float p0 = __expf(v0);
                const float p1 = __expf(v1);
                const float p2 = __expf(v2);
                const float p3 = __expf(v3);
                lsum0 += p0 + p1;
                lsum8 += p2 + p3;
                const int kc = jn >> 1, half = jn & 1;
                uint32_t h01 = pack_hi(p0, p1);
                uint32_t h23 = pack_hi(p2, p3);
                ph[kc][half*2 + 0] = h01;
                ph[kc][half*2 + 1] = h23;
                pl[kc][half*2 + 0] = pack_lo(p0, p1, h01);
                pl[kc][half*2 + 1] = pack_lo(p2, p3, h23);
            }

            #pragma unroll
            for (int kc = 0; kc < 4; kc++) {
                #pragma unroll
                for (int jdp = 0; jdp < 4; jdp++) {
                    const uint32_t voff =
                        (uint32_t)((kc*16 + vrow_l)*STRB + ((2*jdp + vch)*8)*2);
                    uint32_t vhb[4], vlb[4];
                    ldx4t(vhb, bvh + voff);
                    ldx4t(vlb, bvl + voff);
                    mma16816(dacc[2*jdp],   ph[kc], vhb[0], vhb[1]);
                    mma16816(dacc[2*jdp+1], ph[kc], vhb[2], vhb[3]);
                    mma16816(dacc[2*jdp],   ph[kc], vlb[0], vlb[1]);
                    mma16816(dacc[2*jdp+1], ph[kc], vlb[2], vlb[3]);
                    mma16816(dacc[2*jdp],   pl[kc], vhb[0], vhb[1]);
                    mma16816(dacc[2*jdp+1], pl[kc], vhb[2], vhb[3]);
                }
            }
        }

        // epilogue: quad-reduce row sums, normalize, emit O as bf16 hi/lo
        #pragma unroll
        for (int o_ = 1; o_ < 4; o_ <<= 1) {
            lsum0 += __shfl_xor_sync(0xffffffffu, lsum0, o_);
            lsum8 += __shfl_xor_sync(0xffffffffu, lsum8, o_);
        }
        const float inv0 = 1.0f / lsum0;
        const float inv8 = 1.0f / lsum8;
        #pragma unroll
        for (int jd = 0; jd < 8; jd++) {
            const int col = jd*8 + 2*t;
            const float v0 = dacc[jd][0]*inv0, v1 = dacc[jd][1]*inv0;
            const float v2 = dacc[jd][2]*inv8, v3 = dacc[jd][3]*inv8;
            uint32_t h01 = pack_hi(v0, v1), l01 = pack_lo(v0, v1, h01);
            uint32_t h23 = pack_hi(v2, v3), l23 = pack_lo(v2, v3, h23);
            *reinterpret_cast<uint32_t*>(g_Ohi + off + row0*64 + col) = h01;
            *reinterpret_cast<uint32_t*>(g_Olo + off + row0*64 + col) = l01;
            *reinterpret_cast<uint32_t*>(g_Ohi + off + row8*64 + col) = h23;
            *reinterpret_cast<uint32_t*>(g_Olo + off + row8*64 + col) = l23;
        }
    }
}

// ---------------------------------------------------------------------------
// Kernel 3: HMMA output projection.  CTA = 32 rows, 2 warps, K streamed over
// 12 head-chunks with cp.async double buffering.  out = O @ Wo + bo (fp32).
// ---------------------------------------------------------------------------
#define PJ_OH0 0
#define PJ_OL0 (32*STRB)
#define PJ_WH0 (2*32*STRB)
#define PJ_WL0 (2*32*STRB + 64*STRB)
#define PJ_BUF (2*32*STRB + 2*64*STRB)   // 27648 per buffer
#define PROJ_SMEM (2*PJ_BUF)

__global__ __launch_bounds__(64) void proj_kernel(
    const float* __restrict__ bo, float* __restrict__ out)
{
    extern __shared__ __align__(16) char smn[];
    const uint32_t sb = smem_u32(smn);
    const int blk  = blockIdx.x;     // 32 rows each
    const int tid  = threadIdx.x;
    const int wid  = tid >> 5;       // 2 warps x 16 rows
    const int lane = tid & 31;
    const int g    = lane >> 2;
    const int t    = lane & 3;
    const int qrow_l = lane & 15;
    const int qch    = lane >> 4;
    const int vrow_l = ((lane >> 3) & 1)*8 + (lane & 7);
    const int vch    = (lane >> 4) & 1;

    const int rgb   = blk*32;
    const int bi    = rgb >> 11;
    const int sbase = rgb & (SEQ-1);

    // stage chunk 0 into buffer 0
    #pragma unroll
    for (int i = tid; i < 256; i += 64) {
        const int r = i >> 3, c = i & 7;
        const int gidx = ((bi*NH + 0)*SEQ + sbase + r)*64 + c*8;
        cp16(smn + PJ_OH0 + r*STRB + c*16, g_Ohi + gidx);
        cp16(smn + PJ_OL0 + r*STRB + c*16, g_Olo + gidx);
    }
    #pragma unroll
    for (int i = tid; i < 512; i += 64) {
        const int r = i >> 3, c = i & 7;
        cp16(smn + PJ_WH0 + r*STRB + c*16, g_Woh + r*64 + c*8);
        cp16(smn + PJ_WL0 + r*STRB + c*16, g_Wol + r*64 + c*8);
    }
    cp_commit();

    float dacc[8][4];
    #pragma unroll
    for (int j = 0; j < 8; j++)
        #pragma unroll
        for (int e = 0; e < 4; e++) dacc[j][e] = 0.f;

    for (int h = 0; h < NH; ++h) {
        const int buf = h & 1;
        cp_wait0();
        __syncthreads();

        if (h + 1 < NH) {
            const int nb = (buf ^ 1) * PJ_BUF;
            const int nh = h + 1;
            #pragma unroll
            for (int i = tid; i < 256; i += 64) {
                const int r = i >> 3, c = i & 7;
                const int gidx = ((bi*NH + nh)*SEQ + sbase + r)*64 + c*8;
                cp16(smn + nb + PJ_OH0 + r*STRB + c*16, g_Ohi + gidx);
                cp16(smn + nb + PJ_OL0 + r*STRB + c*16, g_Olo + gidx);
            }
            #pragma unroll
            for (int i = tid; i < 512; i += 64) {
                const int r = i >> 3, c = i & 7;
                cp16(smn + nb + PJ_WH0 + r*STRB + c*16, g_Woh + (nh*64 + r)*64 + c*8);
                cp16(smn + nb + PJ_WL0 + r*STRB + c*16, g_Wol + (nh*64 + r)*64 + c*8);
            }
        }
        cp_commit();

        const uint32_t ohb = sb + buf*PJ_BUF + PJ_OH0;
        const uint32_t olb = sb + buf*PJ_BUF + PJ_OL0;
        const uint32_t whb = sb + buf*PJ_BUF + PJ_WH0;
        const uint32_t wlb = sb + buf*PJ_BUF + PJ_WL0;

        #pragma unroll
        for (int kc = 0; kc < 4; kc++) {
            uint32_t ah[4], al[4];
            const uint32_t aoff = (uint32_t)((wid*16 + qrow_l)*STRB + (kc*16 + qch*8)*2);
            ldx4(ah, ohb + aoff);
            ldx4(al, olb + aoff);
            #pragma unroll
            for (int jdp = 0; jdp < 4; jdp++) {
                const uint32_t voff = (uint32_t)((kc*16 + vrow_l)*STRB + ((2*jdp + vch)*8)*2);
                uint32_t bhf[4], blf[4];
                ldx4t(bhf, whb + voff);
                ldx4t(blf, wlb + voff);
                mma16816(dacc[2*jdp],   ah, bhf[0], bhf[1]);
                mma16816(dacc[2*jdp+1], ah, bhf[2], bhf[3]);
                mma16816(dacc[2*jdp],   ah, blf[0], blf[1]);
                mma16816(dacc[2*jdp+1], ah, blf[2], blf[3]);
                mma16816(dacc[2*jdp],   al, bhf[0], bhf[1]);
                mma16816(dacc[2*jdp+1], al, bhf[2], bhf[3]);
            }
        }
    }

    const int row0 = rgb + wid*16 + g;
    const int row8 = row0 + 8;
    #pragma unroll
    for (int jd = 0; jd < 8; jd++) {
        const int col = jd*8 + 2*t;
        const float b0 = bo[col], b1 = bo[col+1];
        *reinterpret_cast<float2*>(out + row0*64 + col) =
            make_float2(dacc[jd][0] + b0, dacc[jd][1] + b1);
        *reinterpret_cast<float2*>(out + row8*64 + col) =
            make_float2(dacc[jd][2] + b0, dacc[jd][3] + b1);
    }
}

// ---------------------------------------------------------------------------
extern "C" void kernel_launch(void* const* d_in, const int* in_sizes, int n_in,
                              void* d_out, int out_size)
{
    (void)in_sizes; (void)n_in; (void)out_size;
    const float* x  = (const float*)d_in[0];
    const float* Wq = (const float*)d_in[1];
    const float* bq = (const float*)d_in[2];
    const float* Wk = (const float*)d_in[3];
    const float* bk = (const float*)d_in[4];
    const float* Wv = (const float*)d_in[5];
    const float* bv = (const float*)d_in[6];
    const float* Wo = (const float*)d_in[7];
    const float* bo = (const float*)d_in[8];
    float* out = (float*)d_out;

    cudaFuncSetAttribute(attn_kernel,
                         cudaFuncAttributeMaxDynamicSharedMemorySize,
                         ATTN_SMEM_BYTES);
    cudaFuncSetAttribute(qkv_kernel,
                         cudaFuncAttributeMaxDynamicSharedMemorySize,
                         QKV2_SMEM);
    cudaFuncSetAttribute(proj_kernel,
                         cudaFuncAttributeMaxDynamicSharedMemorySize,
                         PROJ_SMEM);

    prep_kernel<<<48, 256>>>(Wo);
    qkv_kernel<<<dim3(64, 12), 128, QKV2_SMEM>>>(x, Wq, bq, Wk, bk, Wv, bv);
    attn_kernel<<<N_CTAS, 256, ATTN_SMEM_BYTES>>>();
    proj_kernel<<<128, 64, PROJ_SMEM>>>(bo, out);
}

// round 12
// speedup vs baseline: 3.0400x; 1.1618x over previous
#include <cuda_runtime.h>
#include <cuda_bf16.h>
#include <cuda_fp16.h>
#include <cstdint>

#define NUM_B 2
#define SEQ   2048
#define HD    64
#define NH    12
#define NEGV  (-99999.0f)
#define TOT   (NUM_B*NH*SEQ*HD)
#define N_ITEMS (16*24)
#define N_CTAS  296

// ---- cp.async ----
__device__ __forceinline__ void cp16(void* smem_dst, const void* gmem_src) {
    unsigned s = (unsigned)__cvta_generic_to_shared(smem_dst);
    asm volatile("cp.async.ca.shared.global [%0], [%1], 16;\n" :: "r"(s), "l"(gmem_src));
}
__device__ __forceinline__ void cp_commit() { asm volatile("cp.async.commit_group;\n"); }
__device__ __forceinline__ void cp_wait0()  { asm volatile("cp.async.wait_group 0;\n" ::: "memory"); }

__device__ __forceinline__ uint32_t smem_u32(const void* p) {
    uint32_t a;
    asm("{ .reg .u64 t; cvta.to.shared.u64 t, %1; cvt.u32.u64 %0, t; }" : "=r"(a) : "l"(p));
    return a;
}

// ---- warp MMA primitives ----
__device__ __forceinline__ void mma16816(float* d, const uint32_t* a, uint32_t b0, uint32_t b1) {
    asm volatile("mma.sync.aligned.m16n8k16.row.col.f32.bf16.bf16.f32 "
                 "{%0,%1,%2,%3}, {%4,%5,%6,%7}, {%8,%9}, {%0,%1,%2,%3};"
                 : "+f"(d[0]), "+f"(d[1]), "+f"(d[2]), "+f"(d[3])
                 : "r"(a[0]), "r"(a[1]), "r"(a[2]), "r"(a[3]), "r"(b0), "r"(b1));
}
__device__ __forceinline__ void mmah(float* d, const uint32_t* a, uint32_t b0, uint32_t b1) {
    asm volatile("mma.sync.aligned.m16n8k16.row.col.f32.f16.f16.f32 "
                 "{%0,%1,%2,%3}, {%4,%5,%6,%7}, {%8,%9}, {%0,%1,%2,%3};"
                 : "+f"(d[0]), "+f"(d[1]), "+f"(d[2]), "+f"(d[3])
                 : "r"(a[0]), "r"(a[1]), "r"(a[2]), "r"(a[3]), "r"(b0), "r"(b1));
}
__device__ __forceinline__ void ldx4(uint32_t* r, uint32_t addr) {
    asm volatile("ldmatrix.sync.aligned.m8n8.x4.shared.b16 {%0,%1,%2,%3}, [%4];"
                 : "=r"(r[0]), "=r"(r[1]), "=r"(r[2]), "=r"(r[3]) : "r"(addr));
}
__device__ __forceinline__ void ldx4t(uint32_t* r, uint32_t addr) {
    asm volatile("ldmatrix.sync.aligned.m8n8.x4.trans.shared.b16 {%0,%1,%2,%3}, [%4];"
                 : "=r"(r[0]), "=r"(r[1]), "=r"(r[2]), "=r"(r[3]) : "r"(addr));
}

// ---- bf16 pack ----
__device__ __forceinline__ uint32_t packbf2(__nv_bfloat16 a, __nv_bfloat16 b) {
    __nv_bfloat162 t; t.x = a; t.y = b; return *reinterpret_cast<uint32_t*>(&t);
}
__device__ __forceinline__ uint32_t pack_hi(float a, float b) {
    return packbf2(__float2bfloat16_rn(a), __float2bfloat16_rn(b));
}
__device__ __forceinline__ uint32_t pack_lo(float a, float b, uint32_t hi) {
    __nv_bfloat162 h = *reinterpret_cast<__nv_bfloat162*>(&hi);
    return packbf2(__float2bfloat16_rn(a - __bfloat162float(h.x)),
                   __float2bfloat16_rn(b - __bfloat162float(h.y)));
}
// ---- fp16 pack (Q/K path only; values O(1), range-safe) ----
__device__ __forceinline__ uint32_t packh2(float a, float b) {
    __half2 t = __floats2half2_rn(a, b);
    return *reinterpret_cast<uint32_t*>(&t);
}
__device__ __forceinline__ uint32_t packh2_lo(float a, float b, uint32_t hi) {
    __half2 h = *reinterpret_cast<__half2*>(&hi);
    return packh2(a - __half2float(h.x), b - __half2float(h.y));
}

// ---- global scratch ----
__device__ __align__(16) __half g_Q[TOT];           // fp16 single
__device__ __align__(16) __half g_Kh[TOT];          // fp16 hi
__device__ __align__(16) __half g_Kl[TOT];          // fp16 lo
__device__ __align__(16) __nv_bfloat16 g_Vh[TOT];   // bf16 hi
__device__ __align__(16) __nv_bfloat16 g_Vl[TOT];   // bf16 lo
__device__ __align__(16) __nv_bfloat16 g_Ohi[TOT];
__device__ __align__(16) __nv_bfloat16 g_Olo[TOT];
__device__ __align__(16) __nv_bfloat16 g_Woh[768*64];
__device__ __align__(16) __nv_bfloat16 g_Wol[768*64];
__device__ int g_counter;

#define STRB 144   // 16-bit row stride bytes (64 vals + pad)

// ---------------------------------------------------------------------------
// Kernel 0: prep — split Wo into bf16 hi/lo, reset work counter.
// ---------------------------------------------------------------------------
__global__ __launch_bounds__(256) void prep_kernel(const float* __restrict__ Wo)
{
    const int i = blockIdx.x*256 + threadIdx.x;
    if (i == 0) g_counter = 0;
    float4 v = reinterpret_cast<const float4*>(Wo)[i];
    uint32_t h01 = pack_hi(v.x, v.y), h23 = pack_hi(v.z, v.w);
    uint32_t l01 = pack_lo(v.x, v.y, h01), l23 = pack_lo(v.z, v.w, h23);
    *reinterpret_cast<uint2*>(g_Woh + i*4) = make_uint2(h01, h23);
    *reinterpret_cast<uint2*>(g_Wol + i*4) = make_uint2(l01, l23);
}

// ---------------------------------------------------------------------------
// Kernel 1: HMMA fused QKV projection (bf16 3-term internally).
// Outputs: Q fp16 single, K fp16 hi/lo, V bf16 hi/lo.
// ---------------------------------------------------------------------------
#define QK2_XH 0
#define QK2_XL (64*STRB)
#define QK2_WB (2*64*STRB)
#define QKV2_SMEM (QK2_WB + 6*64*STRB)

__global__ __launch_bounds__(128) void qkv_kernel(
    const float* __restrict__ x,
    const float* __restrict__ Wq, const float* __restrict__ bq,
    const float* __restrict__ Wk, const float* __restrict__ bk,
    const float* __restrict__ Wv, const float* __restrict__ bv)
{
    extern __shared__ __align__(16) char smn[];
    const uint32_t sb = smem_u32(smn);
    const int tile = blockIdx.x;
    const int head = blockIdx.y;
    const int tid  = threadIdx.x;
    const int wid  = tid >> 5;
    const int lane = tid & 31;
    const int g    = lane >> 2;
    const int t    = lane & 3;
    const int qrow_l = lane & 15;
    const int qch    = lane >> 4;
    const int vrow_l = ((lane >> 3) & 1)*8 + (lane & 7);
    const int vch    = (lane >> 4) & 1;

    #pragma unroll
    for (int i = tid; i < 1024; i += 128) {
        const int r = i >> 4, c4 = (i & 15) << 2;
        float4 v = *reinterpret_cast<const float4*>(x + (tile*64 + r)*64 + c4);
        uint32_t h01 = pack_hi(v.x, v.y), h23 = pack_hi(v.z, v.w);
        uint32_t l01 = pack_lo(v.x, v.y, h01), l23 = pack_lo(v.z, v.w, h23);
        *reinterpret_cast<uint2*>(smn + QK2_XH + r*STRB + c4*2) = make_uint2(h01, h23);
        *reinterpret_cast<uint2*>(smn + QK2_XL + r*STRB + c4*2) = make_uint2(l01, l23);
    }
    {
        const float* const Wm[3] = {Wq, Wk, Wv};
        #pragma unroll
        for (int m = 0; m < 3; m++) {
            const float* W = Wm[m];
            const int base = QK2_WB + m*(2*64*STRB);
            #pragma unroll
            for (int i = tid; i < 1024; i += 128) {
                const int r = i >> 4, c4 = (i & 15) << 2;
                float4 v = *reinterpret_cast<const float4*>(W + r*768 + head*64 + c4);
                uint32_t h01 = pack_hi(v.x, v.y), h23 = pack_hi(v.z, v.w);
                uint32_t l01 = pack_lo(v.x, v.y, h01), l23 = pack_lo(v.z, v.w, h23);
                *reinterpret_cast<uint2*>(smn + base + r*STRB + c4*2) = make_uint2(h01, h23);
                *reinterpret_cast<uint2*>(smn + base + 64*STRB + r*STRB + c4*2) = make_uint2(l01, l23);
            }
        }
    }
    __syncthreads();

    uint32_t ah[4][4], al[4][4];
    #pragma unroll
    for (int kc = 0; kc < 4; kc++) {
        const uint32_t aoff = (uint32_t)((wid*16 + qrow_l)*STRB + (kc*16 + qch*8)*2);
        ldx4(ah[kc], sb + QK2_XH + aoff);
        ldx4(al[kc], sb + QK2_XL + aoff);
    }

    const int rg0 = tile*64 + wid*16 + g;
    const int bi  = rg0 >> 11;
    const int si0 = rg0 & (SEQ-1);
    const int bh  = bi*NH + head;
    const float* const Bm[3] = {bq, bk, bv};

    #pragma unroll
    for (int m = 0; m < 3; m++) {
        const uint32_t whb = sb + QK2_WB + m*(2*64*STRB);
        const uint32_t wlb = whb + 64*STRB;
        float dacc[8][4];
        #pragma unroll
        for (int j = 0; j < 8; j++)
            #pragma unroll
            for (int e = 0; e < 4; e++) dacc[j][e] = 0.f;

        #pragma unroll
        for (int kc = 0; kc < 4; kc++) {
            #pragma unroll
            for (int jdp = 0; jdp < 4; jdp++) {
                const uint32_t voff = (uint32_t)((kc*16 + vrow_l)*STRB + ((2*jdp + vch)*8)*2);
                uint32_t bhf[4], blf[4];
                ldx4t(bhf, whb + voff);
                ldx4t(blf, wlb + voff);
                mma16816(dacc[2*jdp],   ah[kc], bhf[0], bhf[1]);
                mma16816(dacc[2*jdp+1], ah[kc], bhf[2], bhf[3]);
                mma16816(dacc[2*jdp],   ah[kc], blf[0], blf[1]);
                mma16816(dacc[2*jdp+1], ah[kc], blf[2], blf[3]);
                mma16816(dacc[2*jdp],   al[kc], bhf[0], bhf[1]);
                mma16816(dacc[2*jdp+1], al[kc], bhf[2], bhf[3]);
            }
        }

        const float* bias = Bm[m] + head*64;
        #pragma unroll
        for (int jd = 0; jd < 8; jd++) {
            const int col = jd*8 + 2*t;
            const float b0 = bias[col], b1 = bias[col+1];
            const float v0 = dacc[jd][0] + b0, v1 = dacc[jd][1] + b1;
            const float v2 = dacc[jd][2] + b0, v3 = dacc[jd][3] + b1;
            const int idx0 = (bh*SEQ + si0)*HD + col;
            const int idx8 = idx0 + 8*HD;
            if (m == 0) {
                *reinterpret_cast<uint32_t*>(g_Q + idx0) = packh2(v0, v1);
                *reinterpret_cast<uint32_t*>(g_Q + idx8) = packh2(v2, v3);
            } else if (m == 1) {
                uint32_t h01 = packh2(v0, v1), h23 = packh2(v2, v3);
                *reinterpret_cast<uint32_t*>(g_Kh + idx0) = h01;
                *reinterpret_cast<uint32_t*>(g_Kl + idx0) = packh2_lo(v0, v1, h01);
                *reinterpret_cast<uint32_t*>(g_Kh + idx8) = h23;
                *reinterpret_cast<uint32_t*>(g_Kl + idx8) = packh2_lo(v2, v3, h23);
            } else {
                uint32_t h01 = pack_hi(v0, v1), h23 = pack_hi(v2, v3);
                *reinterpret_cast<uint32_t*>(g_Vh + idx0) = h01;
                *reinterpret_cast<uint32_t*>(g_Vl + idx0) = pack_lo(v0, v1, h01);
                *reinterpret_cast<uint32_t*>(g_Vh + idx8) = h23;
                *reinterpret_cast<uint32_t*>(g_Vl + idx8) = pack_lo(v2, v3, h23);
            }
        }
    }
}

// ---------------------------------------------------------------------------
// Kernel 2: flash attention.  QK = fp16 2-term (qh*(kh+kl)), softmax with
// unscaled exp (fp32/bf16 range), PV = bf16 3-term (proven R8/R9 path).
// ---------------------------------------------------------------------------
#define SM_ITEM 0
#define SM_Q    16
#define SM_KH0  (SM_Q + 128*STRB)
#define SM_KL0  (SM_KH0 + 64*STRB)
#define SM_VH0  (SM_KL0 + 64*STRB)
#define SM_VL0  (SM_VH0 + 64*STRB)
#define SM_KH1  (SM_VL0 + 64*STRB)
#define SM_KL1  (SM_KH1 + 64*STRB)
#define SM_VH1  (SM_KL1 + 64*STRB)
#define SM_VL1  (SM_VH1 + 64*STRB)
#define ATTN_SMEM_BYTES (SM_VL1 + 64*STRB)

__global__ __launch_bounds__(256, 2) void attn_kernel()
{
    extern __shared__ __align__(16) char smn[];
    const uint32_t sb = smem_u32(smn);
    const int tid  = threadIdx.x;
    const int wid  = tid >> 5;
    const int lane = tid & 31;
    const int g    = lane >> 2;
    const int t    = lane & 3;
    int* itp = reinterpret_cast<int*>(smn + SM_ITEM);

    const int qrow_l = (lane & 15);
    const int qch    = (lane >> 4);
    const int krow_l = ((lane >> 4) & 1)*8 + (lane & 7);
    const int kch    = (lane >> 3) & 1;
    const int vrow_l = ((lane >> 3) & 1)*8 + (lane & 7);
    const int vch    = (lane >> 4) & 1;

    for (;;) {
        __syncthreads();
        if (tid == 0) *itp = atomicAdd(&g_counter, 1);
        __syncthreads();
        const int it = *itp;
        if (it >= N_ITEMS) return;

        const int qr = it / 24;
        const int qx = 15 - qr;
        const int bh = it - qr * 24;
        const int qb  = qx * 128;
        const int off = bh * SEQ * HD;

        #pragma unroll
        for (int i = tid; i < 1024; i += 256) {
            const int r = i >> 3, c = i & 7;
            cp16(smn + SM_Q + r*STRB + c*16, g_Q + off + (qb + r)*64 + c*8);
        }
        #pragma unroll
        for (int i = tid; i < 512; i += 256) {
            const int r = i >> 3, c = i & 7;
            cp16(smn + SM_KH0 + r*STRB + c*16, g_Kh + off + r*64 + c*8);
            cp16(smn + SM_KL0 + r*STRB + c*16, g_Kl + off + r*64 + c*8);
            cp16(smn + SM_VH0 + r*STRB + c*16, g_Vh + off + r*64 + c*8);
            cp16(smn + SM_VL0 + r*STRB + c*16, g_Vl + off + r*64 + c*8);
        }
        cp_commit();

        float dacc[8][4];
        #pragma unroll
        for (int j = 0; j < 8; j++)
            #pragma unroll
            for (int e = 0; e < 4; e++) dacc[j][e] = 0.f;
        float lsum0 = 0.f, lsum8 = 0.f;

        const int row0 = qb + wid*16 + g;
        const int row8 = row0 + 8;

        const int nkt = 2*qx + 2;
        for (int kt = 0; kt < nkt; ++kt) {
            const int kb  = kt * 64;
            const int buf = kt & 1;
            cp_wait0();
            __syncthreads();

            if (kt + 1 < nkt) {
                const int nkb = kb + 64;
                const uint32_t okh = buf ? SM_KH0 : SM_KH1;
                const uint32_t okl = buf ? SM_KL0 : SM_KL1;
                const uint32_t ovh = buf ? SM_VH0 : SM_VH1;
                const uint32_t ovl = buf ? SM_VL0 : SM_VL1;
                #pragma unroll
                for (int i = tid; i < 512; i += 256) {
                    const int r = i >> 3, c = i & 7;
                    cp16(smn + okh + r*STRB + c*16, g_Kh + off + (nkb + r)*64 + c*8);
                    cp16(smn + okl + r*STRB + c*16, g_Kl + off + (nkb + r)*64 + c*8);
                    cp16(smn + ovh + r*STRB + c*16, g_Vh + off + (nkb + r)*64 + c*8);
                    cp16(smn + ovl + r*STRB + c*16, g_Vl + off + (nkb + r)*64 + c*8);
                }
            }
            cp_commit();

            const uint32_t bkh = sb + (buf ? SM_KH1 : SM_KH0);
            const uint32_t bkl = sb + (buf ? SM_KL1 : SM_KL0);
            const uint32_t bvh = sb + (buf ? SM_VH1 : SM_VH0);
            const uint32_t bvl = sb + (buf ? SM_VL1 : SM_VL0);

            // ---- S = Q @ K^T : fp16 2-term qh*kh + qh*kl ----
            float sacc[8][4];
            #pragma unroll
            for (int j = 0; j < 8; j++)
                #pragma unroll
                for (int e = 0; e < 4; e++) sacc[j][e] = 0.f;

            #pragma unroll
            for (int ks = 0; ks < 4; ks++) {
                uint32_t qh[4];
                const uint32_t qoff = (uint32_t)((wid*16 + qrow_l)*STRB + (ks*16 + qch*8)*2);
                ldx4(qh, sb + SM_Q + qoff);
                #pragma unroll
                for (int jp = 0; jp < 4; jp++) {
                    const uint32_t koff = (uint32_t)((jp*16 + krow_l)*STRB + (ks*16 + kch*8)*2);
                    uint32_t khb[4], klb[4];
                    ldx4(khb, bkh + koff);
                    ldx4(klb, bkl + koff);
                    mmah(sacc[2*jp],   qh, khb[0], khb[1]);
                    mmah(sacc[2*jp+1], qh, khb[2], khb[3]);
                    mmah(sacc[2*jp],   qh, klb[0], klb[1]);
                    mmah(sacc[2*jp+1], qh, klb[2], klb[3]);
                }
            }

            // ---- mask + exp (fixed max=0, unscaled) + P bf16 hi/lo fragments ----
            uint32_t ph[4][4], pl[4][4];
            #pragma unroll
            for (int jn = 0; jn < 8; jn++) {
                const int col = kb + jn*8 + 2*t;
                float v0 = sacc[jn][0], v1 = sacc[jn][1];
                float v2 = sacc[jn][2], v3 = sacc[jn][3];
                if (col     > row0 || v0 == 0.0f) v0 = NEGV;
                if (col + 1 > row0 || v1 == 0.0f) v1 = NEGV;
                if (col     > row8 || v2 == 0.0f) v2 = NEGV;
                if (col + 1 > row8 || v3 == 0.0f) v3 = NEGV;
                const float p0 = __expf(v0);
                const float p1 = __expf(v1);
                const float p2 = __expf(v2);
                const float p3 = __expf(v3);
                lsum0 += p0 + p1;
                lsum8 += p2 + p3;
                const int kc = jn >> 1, half = jn & 1;
                uint32_t h01 = pack_hi(p0, p1);
                uint32_t h23 = pack_hi(p2, p3);
                ph[kc][half*2 + 0] = h01;
                ph[kc][half*2 + 1] = h23;
                pl[kc][half*2 + 0] = pack_lo(p0, p1, h01);
                pl[kc][half*2 + 1] = pack_lo(p2, p3, h23);
            }

            // ---- D += P @ V : bf16 3-term ph*vh + ph*vl + pl*vh ----
            #pragma unroll
            for (int kc = 0; kc < 4; kc++) {
                #pragma unroll
                for (int jdp = 0; jdp < 4; jdp++) {
                    const uint32_t voff =
                        (uint32_t)((kc*16 + vrow_l)*STRB + ((2*jdp + vch)*8)*2);
                    uint32_t vhb[4], vlb[4];
                    ldx4t(vhb, bvh + voff);
                    ldx4t(vlb, bvl + voff);
                    mma16816(dacc[2*jdp],   ph[kc], vhb[0], vhb[1]);
                    mma16816(dacc[2*jdp+1], ph[kc], vhb[2], vhb[3]);
                    mma16816(dacc[2*jdp],   ph[kc], vlb[0], vlb[1]);
                    mma16816(dacc[2*jdp+1], ph[kc], vlb[2], vlb[3]);
                    mma16816(dacc[2*jdp],   pl[kc], vhb[0], vhb[1]);
                    mma16816(dacc[2*jdp+1], pl[kc], vhb[2], vhb[3]);
                }
            }
        }

        // ---- epilogue: quad-reduce sums, normalize, emit O bf16 hi/lo ----
        #pragma unroll
        for (int o_ = 1; o_ < 4; o_ <<= 1) {
            lsum0 += __shfl_xor_sync(0xffffffffu, lsum0, o_);
            lsum8 += __shfl_xor_sync(0xffffffffu, lsum8, o_);
        }
        const float inv0 = 1.0f / lsum0;
        const float inv8 = 1.0f / lsum8;
        #pragma unroll
        for (int jd = 0; jd < 8; jd++) {
            const int col = jd*8 + 2*t;
            const float v0 = dacc[jd][0]*inv0, v1 = dacc[jd][1]*inv0;
            const float v2 = dacc[jd][2]*inv8, v3 = dacc[jd][3]*inv8;
            uint32_t h01 = pack_hi(v0, v1), l01 = pack_lo(v0, v1, h01);
            uint32_t h23 = pack_hi(v2, v3), l23 = pack_lo(v2, v3, h23);
            *reinterpret_cast<uint32_t*>(g_Ohi + off + row0*64 + col) = h01;
            *reinterpret_cast<uint32_t*>(g_Olo + off + row0*64 + col) = l01;
            *reinterpret_cast<uint32_t*>(g_Ohi + off + row8*64 + col) = h23;
            *reinterpret_cast<uint32_t*>(g_Olo + off + row8*64 + col) = l23;
        }
    }
}

// ---------------------------------------------------------------------------
// Kernel 3: HMMA output projection (bf16 3-term, unchanged from R9).
// ---------------------------------------------------------------------------
#define PJ_OH0 0
#define PJ_OL0 (32*STRB)
#define PJ_WH0 (2*32*STRB)
#define PJ_WL0 (2*32*STRB + 64*STRB)
#define PJ_BUF (2*32*STRB + 2*64*STRB)
#define PROJ_SMEM (2*PJ_BUF)

__global__ __launch_bounds__(64) void proj_kernel(
    const float* __restrict__ bo, float* __restrict__ out)
{
    extern __shared__ __align__(16) char smn[];
    const uint32_t sb = smem_u32(smn);
    const int blk  = blockIdx.x;
    const int tid  = threadIdx.x;
    const int wid  = tid >> 5;
    const int lane = tid & 31;
    const int g    = lane >> 2;
    const int t    = lane & 3;
    const int qrow_l = lane & 15;
    const int qch    = lane >> 4;
    const int vrow_l = ((lane >> 3) & 1)*8 + (lane & 7);
    const int vch    = (lane >> 4) & 1;

    const int rgb   = blk*32;
    const int bi    = rgb >> 11;
    const int sbase = rgb & (SEQ-1);

    #pragma unroll
    for (int i = tid; i < 256; i += 64) {
        const int r = i >> 3, c = i & 7;
        const int gidx = ((bi*NH + 0)*SEQ + sbase + r)*64 + c*8;
        cp16(smn + PJ_OH0 + r*STRB + c*16, g_Ohi + gidx);
        cp16(smn + PJ_OL0 + r*STRB + c*16, g_Olo + gidx);
    }
    #pragma unroll
    for (int i = tid; i < 512; i += 64) {
        const int r = i >> 3, c = i & 7;
        cp16(smn + PJ_WH0 + r*STRB + c*16, g_Woh + r*64 + c*8);
        cp16(smn + PJ_WL0 + r*STRB + c*16, g_Wol + r*64 + c*8);
    }
    cp_commit();

    float dacc[8][4];
    #pragma unroll
    for (int j = 0; j < 8; j++)
        #pragma unroll
        for (int e = 0; e < 4; e++) dacc[j][e] = 0.f;

    for (int h = 0; h < NH; ++h) {
        const int buf = h & 1;
        cp_wait0();
        __syncthreads();

        if (h + 1 < NH) {
            const int nb = (buf ^ 1) * PJ_BUF;
            const int nh = h + 1;
            #pragma unroll
            for (int i = tid; i < 256; i += 64) {
                const int r = i >> 3, c = i & 7;
                const int gidx = ((bi*NH + nh)*SEQ + sbase + r)*64 + c*8;
                cp16(smn + nb + PJ_OH0 + r*STRB + c*16, g_Ohi + gidx);
                cp16(smn + nb + PJ_OL0 + r*STRB + c*16, g_Olo + gidx);
            }
            #pragma unroll
            for (int i = tid; i < 512; i += 64) {
                const int r = i >> 3, c = i & 7;
                cp16(smn + nb + PJ_WH0 + r*STRB + c*16, g_Woh + (nh*64 + r)*64 + c*8);
                cp16(smn + nb + PJ_WL0 + r*STRB + c*16, g_Wol + (nh*64 + r)*64 + c*8);
            }
        }
        cp_commit();

        const uint32_t ohb = sb + buf*PJ_BUF + PJ_OH0;
        const uint32_t olb = sb + buf*PJ_BUF + PJ_OL0;
        const uint32_t whb = sb + buf*PJ_BUF + PJ_WH0;
        const uint32_t wlb = sb + buf*PJ_BUF + PJ_WL0;

        #pragma unroll
        for (int kc = 0; kc < 4; kc++) {
            uint32_t ah[4], al[4];
            const uint32_t aoff = (uint32_t)((wid*16 + qrow_l)*STRB + (kc*16 + qch*8)*2);
            ldx4(ah, ohb + aoff);
            ldx4(al, olb + aoff);
            #pragma unroll
            for (int jdp = 0; jdp < 4; jdp++) {
                const uint32_t voff = (uint32_t)((kc*16 + vrow_l)*STRB + ((2*jdp + vch)*8)*2);
                uint32_t bhf[4], blf[4];
                ldx4t(bhf, whb + voff);
                ldx4t(blf, wlb + voff);
                mma16816(dacc[2*jdp],   ah, bhf[0], bhf[1]);
                mma16816(dacc[2*jdp+1], ah, bhf[2], bhf[3]);
                mma16816(dacc[2*jdp],   ah, blf[0], blf[1]);
                mma16816(dacc[2*jdp+1], ah, blf[2], blf[3]);
                mma16816(dacc[2*jdp],   al, bhf[0], bhf[1]);
                mma16816(dacc[2*jdp+1], al, bhf[2], bhf[3]);
            }
        }
    }

    const int row0 = rgb + wid*16 + g;
    const int row8 = row0 + 8;
    #pragma unroll
    for (int jd = 0; jd < 8; jd++) {
        const int col = jd*8 + 2*t;
        const float b0 = bo[col], b1 = bo[col+1];
        *reinterpret_cast<float2*>(out + row0*64 + col) =
            make_float2(dacc[jd][0] + b0, dacc[jd][1] + b1);
        *reinterpret_cast<float2*>(out + row8*64 + col) =
            make_float2(dacc[jd][2] + b0, dacc[jd][3] + b1);
    }
}

// ---------------------------------------------------------------------------
extern "C" void kernel_launch(void* const* d_in, const int* in_sizes, int n_in,
                              void* d_out, int out_size)
{
    (void)in_sizes; (void)n_in; (void)out_size;
    const float* x  = (const float*)d_in[0];
    const float* Wq = (const float*)d_in[1];
    const float* bq = (const float*)d_in[2];
    const float* Wk = (const float*)d_in[3];
    const float* bk = (const float*)d_in[4];
    const float* Wv = (const float*)d_in[5];
    const float* bv = (const float*)d_in[6];
    const float* Wo = (const float*)d_in[7];
    const float* bo = (const float*)d_in[8];
    float* out = (float*)d_out;

    cudaFuncSetAttribute(attn_kernel,
                         cudaFuncAttributeMaxDynamicSharedMemorySize,
                         ATTN_SMEM_BYTES);
    cudaFuncSetAttribute(qkv_kernel,
                         cudaFuncAttributeMaxDynamicSharedMemorySize,
                         QKV2_SMEM);
    cudaFuncSetAttribute(proj_kernel,
                         cudaFuncAttributeMaxDynamicSharedMemorySize,
                         PROJ_SMEM);

    prep_kernel<<<48, 256>>>(Wo);
    qkv_kernel<<<dim3(64, 12), 128, QKV2_SMEM>>>(x, Wq, bq, Wk, bk, Wv, bv);
    attn_kernel<<<N_CTAS, 256, ATTN_SMEM_BYTES>>>();
    proj_kernel<<<128, 64, PROJ_SMEM>>>(bo, out);
}